// round 6
// baseline (speedup 1.0000x reference)
#include <cuda_runtime.h>
#include <stdint.h>

// ---------------------------------------------------------------------------
// BlurModel: 9x9 box blur -> per-patch sequential threshold search ->
// binarize -> morphological close, 2048x2048 f32.
// R6: histogram via chip-wide GLOBAL atomics inside blur (LTS-parallel),
//     k_close at 1024 blocks for occupancy.
// ---------------------------------------------------------------------------

#define W      2048
#define NPX    (W * W)
#define WORDS  64
#define NPAT   64
#define NB     8192
#define VLO    0.40f
#define VSC    40960.0f      // NB / 0.2
#define CAP    512

__device__ float    g_B[NPX];
__device__ unsigned g_hist[NPAT * NB];
__device__ float    g_vd[NPAT];
__device__ float    g_vu[NPAT];
__device__ float    g_ths[NPAT];

// ---------------------------------------------------------------------------
__device__ __forceinline__ int bin_of(float v) {
    float f = (v - VLO) * VSC;
    int b = (int)floorf(f);
    return b < 0 ? 0 : (b > NB - 1 ? NB - 1 : b);
}

// ---------------------------------------------------------------------------
// K1: fused 9x9 separable box blur + per-patch global-atomic histogram.
// Tile 64x32 out, halo 4. 256 threads. Each tile lies within ONE patch.
__global__ void k_blur_hist(const float* __restrict__ x,
                            const float* __restrict__ kptr) {
    __shared__ float raw[40][72];
    __shared__ float hs[40][64];
    int c0 = blockIdx.x << 6;
    int r0 = blockIdx.y << 5;
    int tid = threadIdx.x;
    float kf = __ldg(kptr);
    // patch of this whole tile (64x32 tile cannot cross a 256x256 patch)
    unsigned* hp = g_hist + (((r0 >> 8) << 3) | (c0 >> 8)) * NB;

    for (int i = tid; i < 40 * 72; i += 256) {
        int rr = i / 72, cc = i % 72;
        int gr = r0 - 4 + rr, gc = c0 - 4 + cc;
        float v = 0.0f;
        if (gr >= 0 && gr < W && gc >= 0 && gc < W) v = x[(gr << 11) + gc];
        raw[rr][cc] = v;
    }
    __syncthreads();

    for (int i = tid; i < 40 * 64; i += 256) {
        int rr = i >> 6, cc = i & 63;
        float s = 0.0f;
#pragma unroll
        for (int k = 0; k < 9; ++k) s += raw[rr][cc + k];
        hs[rr][cc] = s;
    }
    __syncthreads();

    for (int i = tid; i < 32 * 64; i += 256) {
        int orow = i >> 6, oc = i & 63;
        float s = 0.0f;
#pragma unroll
        for (int k = 0; k < 9; ++k) s += hs[orow + k][oc];
        float b = s * kf;
        int gr = r0 + orow, gc = c0 + oc;
        g_B[(gr << 11) + gc] = b;
        atomicAdd(&hp[bin_of(b)], 1u);
    }
}

// ---------------------------------------------------------------------------
__device__ float kth_largest(const float* a, int n, int k) {
    if (n <= 0) return 0.5f;
    if (k >= n) k = n - 1;
    for (int i = 0; i < n; ++i) {
        float v = a[i];
        int g = 0, e = 0;
        for (int j = 0; j < n; ++j) {
            if (a[j] > v) g++;
            else if (a[j] == v) e++;
        }
        if (g <= k && k < g + e) return v;
    }
    return a[0];
}

// K2: per-patch order statistics from the GLOBAL histogram. 64 blocks x 1024.
__global__ void k_select() {
    int p = blockIdx.x;
    int t = threadIdx.x;
    int lane = t & 31, wid = t >> 5;
    const unsigned* hist = g_hist + p * NB;

    __shared__ unsigned shist[NB];        // 32 KB local copy (coalesced load)
    __shared__ unsigned warpSuf[32];
    __shared__ int s_binD, s_rD, s_binU, s_rU;
    __shared__ float listD[CAP];
    __shared__ float listU[CAP];
    __shared__ int cntD, cntU;

    // coalesced copy of this patch's histogram (uint4)
    {
        const uint4* h4 = (const uint4*)hist;
        uint4* s4 = (uint4*)shist;
#pragma unroll
        for (int i = 0; i < NB / 4 / 1024; ++i) s4[t + i * 1024] = h4[t + i * 1024];
    }
    if (t == 0) { cntD = 0; cntU = 0; }
    __syncthreads();

    // segment sums: 8 bins per thread
    unsigned segv = 0;
#pragma unroll
    for (int b = 0; b < 8; ++b) segv += shist[t * 8 + b];

    // warp-level inclusive suffix sum
    unsigned suf = segv;
#pragma unroll
    for (int off = 1; off < 32; off <<= 1) {
        unsigned v = __shfl_down_sync(0xFFFFFFFFu, suf, off);
        if (lane + off < 32) suf += v;
    }
    unsigned wtot = __shfl_sync(0xFFFFFFFFu, suf, 0);
    if (lane == 0) warpSuf[wid] = wtot;
    __syncthreads();
    if (wid == 0) {
        unsigned tot = warpSuf[lane];
        unsigned ss = tot;
#pragma unroll
        for (int off = 1; off < 32; off <<= 1) {
            unsigned v = __shfl_down_sync(0xFFFFFFFFu, ss, off);
            if (lane + off < 32) ss += v;
        }
        warpSuf[lane] = ss - tot;          // exclusive suffix of warp totals
    }
    __syncthreads();

    unsigned incl = suf + warpSuf[wid];
    unsigned above = incl - segv;

    bool frame = (p < 8) || (p >= 56) || ((p & 7) == 0) || ((p & 7) == 7);
    float lo = frame ? (0.47f - 0.05f) : 0.47f;
    float hiT = 0.43f;
    const float inv = 1.0f / 65536.0f;
    int Clo = (int)ceilf(lo * 65536.0f);
    while ((float)Clo * inv < lo) Clo++;
    while (Clo > 0 && (float)(Clo - 1) * inv >= lo) Clo--;
    int Chi = (int)floorf(hiT * 65536.0f);
    while ((float)(Chi + 1) * inv <= hiT) Chi++;
    while (Chi > 0 && (float)Chi * inv > hiT) Chi--;
    int kd = Clo - 1;
    int ku = Chi;

    if ((unsigned)kd >= above && (unsigned)kd < incl) {
        unsigned S = above;
        for (int b = 7; b >= 0; --b) {
            unsigned hb = shist[t * 8 + b];
            if ((unsigned)kd < S + hb) { s_binD = t * 8 + b; s_rD = (int)((unsigned)kd - S); break; }
            S += hb;
        }
    }
    if ((unsigned)ku >= above && (unsigned)ku < incl) {
        unsigned S = above;
        for (int b = 7; b >= 0; --b) {
            unsigned hb = shist[t * 8 + b];
            if ((unsigned)ku < S + hb) { s_binU = t * 8 + b; s_rU = (int)((unsigned)ku - S); break; }
            S += hb;
        }
    }
    __syncthreads();

    // candidate collection pass (L2-resident float4 reads)
    int binD = s_binD, binU = s_binU;
    int pr = (p >> 3) << 8, pc = (p & 7) << 8;
    const float4* B4 = (const float4*)g_B;
    for (int i = t; i < 16384; i += 1024) {
        int rr = pr + (i >> 6);
        int cc = pc + ((i & 63) << 2);
        float4 v = B4[((rr << 11) + cc) >> 2];
        float vv[4] = {v.x, v.y, v.z, v.w};
#pragma unroll
        for (int q = 0; q < 4; ++q) {
            int b = bin_of(vv[q]);
            if (b == binD) {
                int pos = atomicAdd(&cntD, 1);
                if (pos < CAP) listD[pos] = vv[q];
            }
            if (binU != binD && b == binU) {
                int pos = atomicAdd(&cntU, 1);
                if (pos < CAP) listU[pos] = vv[q];
            }
        }
    }
    __syncthreads();

    if (t == 0) {
        int nD = cntD < CAP ? cntD : CAP;
        g_vd[p] = kth_largest(listD, nD, s_rD);
        if (binU == binD) {
            g_vu[p] = kth_largest(listD, nD, s_rU);
        } else {
            int nU = cntU < CAP ? cntU : CAP;
            g_vu[p] = kth_largest(listU, nU, s_rU);
        }
    }
}

// ---------------------------------------------------------------------------
// K3: sequential fp32 threshold iteration, exact ulp-space jumps.
__global__ void k_thresh() {
    __shared__ float svd[NPAT], svu[NPAT];
    int tid = threadIdx.x;
    if (tid < NPAT) { svd[tid] = g_vd[tid]; svu[tid] = g_vu[tid]; }
    __syncthreads();
    if (tid != 0) return;

    float t = 0.5f;
    for (int p = 0; p < NPAT; ++p) {
        float vd = svd[p], vu = svu[p];

        int guard = 0;
        while (t >= vd && guard < 1000000) {
            guard++;
            bool jumped = false;
            if (t >= 0.25f && t < 1.0f) {
                float bandlo = (t >= 0.5f) ? 0.5f : 0.25f;
                int ulps     = (t >= 0.5f) ? 839 : 1678;
                float tgt = fmaxf(vd, bandlo);
                int mt = __float_as_int(t), mv = __float_as_int(tgt);
                int kj = (mt - mv) / ulps - 1;
                if (kj > 0) { t = __int_as_float(mt - kj * ulps); jumped = true; }
            }
            if (!jumped) t = t - 5e-5f;
        }

        guard = 0;
        while (t < vu && guard < 2000000) {
            guard++;
            bool jumped = false;
            if (t >= 0.25f && t < 1.0f) {
                float bandhi = (t >= 0.5f) ? 1.0f : 0.5f;
                int ulps     = (t >= 0.5f) ? 84 : 168;
                float tgt = fminf(vu, bandhi);
                int mt = __float_as_int(t), mv = __float_as_int(tgt);
                int kj = (mv - mt) / ulps - 1;
                if (kj > 0) { t = __int_as_float(mt + kj * ulps); jumped = true; }
            }
            if (!jumped) t = t + 5e-6f;
        }
        g_ths[p] = t;
    }
}

// ---------------------------------------------------------------------------
// K4: fully fused close: binarize + dilH + dilV + eroH + eroV + f32 expand.
// Grid (8, 128) = 1024 blocks: tile 256 cols x 16 rows. 256 threads.
// bin tile: rows r0-8..r0+23 (32), words wbase-2..wbase+9 (12)
__global__ void k_close(float* __restrict__ out) {
    __shared__ unsigned sbin[32][12];
    __shared__ unsigned sdh[32][12];   // dilH: word j = global wbase-1+j, j=0..9
    __shared__ unsigned sdv[24][12];   // dilV: row dr = global r0-4+dr
    __shared__ unsigned seh[24][8];    // eroH: out words 0..7
    __shared__ unsigned sfw[16][8];    // final words
    __shared__ float sth[NPAT];
    int wbase = blockIdx.x << 3;
    int r0 = blockIdx.y << 4;
    int tid = threadIdx.x;
    int warpId = tid >> 5, lane = tid & 31;

    if (tid < NPAT) sth[tid] = g_ths[tid];
    __syncthreads();

    // binarize 32 rows x 12 words: warp task = 4 words of one row (float4/lane)
#pragma unroll 2
    for (int tsk = warpId; tsk < 32 * 3; tsk += 8) {
        int row = tsk / 3, qw = tsk - row * 3;
        int tw = (qw << 2) + (lane >> 3);        // 0..11
        int gw = wbase - 2 + tw;
        int gr = r0 - 8 + row;
        unsigned nib = 0;
        if (gr >= 0 && gr < W && gw >= 0 && gw < WORDS) {
            float th = sth[((gr >> 8) << 3) | (gw >> 3)];
            const float4* rp = (const float4*)(g_B + (gr << 11));
            float4 v = rp[(gw << 3) + (lane & 7)];
            nib = (unsigned)(v.x > th) | ((unsigned)(v.y > th) << 1)
                | ((unsigned)(v.z > th) << 2) | ((unsigned)(v.w > th) << 3);
        }
        unsigned x = nib | (__shfl_xor_sync(0xFFFFFFFFu, nib, 1) << 4);
        x = x | (__shfl_xor_sync(0xFFFFFFFFu, x, 2) << 8);
        x = x | (__shfl_xor_sync(0xFFFFFFFFu, x, 4) << 16);
        if ((lane & 7) == 0) sbin[row][tw] = x;
    }
    __syncthreads();

    // horizontal dilate (pad 0): j = 0..9
    for (int i = tid; i < 32 * 10; i += 256) {
        int row = i / 10, j = i - row * 10;
        unsigned curw = sbin[row][j + 1];
        unsigned left = sbin[row][j];
        unsigned right = sbin[row][j + 2];
        unsigned long long a = ((unsigned long long)curw << 32) | left;
        unsigned long long b = ((unsigned long long)right << 32) | curw;
        unsigned o = curw;
#pragma unroll
        for (int k = 1; k <= 4; ++k) {
            o |= (unsigned)(a >> (32 - k));
            o |= (unsigned)(b >> k);
        }
        sdh[row][j] = o;
    }
    __syncthreads();

    // vertical dilate (pad 0): dr = 0..23
    for (int i = tid; i < 24 * 10; i += 256) {
        int dr = i / 10, j = i - dr * 10;
        unsigned o = 0u;
#pragma unroll
        for (int k = 0; k < 9; ++k) o |= sdh[dr + k][j];
        sdv[dr][j] = o;
    }
    __syncthreads();

    // horizontal erode (pad 1 outside image): out word ow (global wbase+ow)
    for (int i = tid; i < 24 * 8; i += 256) {
        int dr = i >> 3, ow = i & 7;
        unsigned curw = sdv[dr][ow + 1];
        unsigned left  = (wbase + ow - 1 >= 0)    ? sdv[dr][ow]     : 0xFFFFFFFFu;
        unsigned right = (wbase + ow + 1 < WORDS) ? sdv[dr][ow + 2] : 0xFFFFFFFFu;
        unsigned long long a = ((unsigned long long)curw << 32) | left;
        unsigned long long b = ((unsigned long long)right << 32) | curw;
        unsigned o = curw;
#pragma unroll
        for (int k = 1; k <= 4; ++k) {
            o &= (unsigned)(a >> (32 - k));
            o &= (unsigned)(b >> k);
        }
        seh[dr][ow] = o;
    }
    __syncthreads();

    // vertical erode (pad 1 outside image): out rows 0..15
    for (int i = tid; i < 16 * 8; i += 256) {
        int orow = i >> 3, ow = i & 7;
        unsigned o = 0xFFFFFFFFu;
#pragma unroll
        for (int k = 0; k < 9; ++k) {
            int gr = r0 + orow - 4 + k;
            unsigned v = (gr >= 0 && gr < W) ? seh[orow + k][ow] : 0xFFFFFFFFu;
            o &= v;
        }
        sfw[orow][ow] = o;
    }
    __syncthreads();

    // expand to f32, float4 stores (16 rows x 64 quads)
    float4* out4 = (float4*)out;
    for (int i = tid; i < 16 * 64; i += 256) {
        int orow = i >> 6;
        int c = (i & 63) << 2;
        unsigned wv = sfw[orow][c >> 5];
        int sh = c & 31;
        float4 o;
        o.x = ((wv >> (sh + 0)) & 1u) ? 1.0f : 0.0f;
        o.y = ((wv >> (sh + 1)) & 1u) ? 1.0f : 0.0f;
        o.z = ((wv >> (sh + 2)) & 1u) ? 1.0f : 0.0f;
        o.w = ((wv >> (sh + 3)) & 1u) ? 1.0f : 0.0f;
        out4[(((r0 + orow) << 11) + (wbase << 5) + c) >> 2] = o;
    }
}

// ---------------------------------------------------------------------------
extern "C" void kernel_launch(void* const* d_in, const int* in_sizes, int n_in,
                              void* d_out, int out_size) {
    const float* x  = (const float*)d_in[0];
    const float* bk = (const float*)d_in[1];
    float* out = (float*)d_out;

    void* hptr = nullptr;
    cudaGetSymbolAddress(&hptr, g_hist);
    cudaMemsetAsync(hptr, 0, sizeof(unsigned) * NPAT * NB, 0);

    dim3 gblur(W / 64, W / 32);
    k_blur_hist<<<gblur, 256>>>(x, bk);
    k_select<<<NPAT, 1024>>>();
    k_thresh<<<1, 64>>>();
    dim3 gclose(8, W / 16);
    k_close<<<gclose, 256>>>(out);
}

// round 7
// speedup vs baseline: 1.1458x; 1.1458x over previous
#include <cuda_runtime.h>
#include <stdint.h>

// ---------------------------------------------------------------------------
// BlurModel: 9x9 box blur -> per-patch sequential threshold search ->
// binarize -> morphological close, 2048x2048 f32.
// R7: R5 base (shared-hist select) + 256x32 close tiles + thresh fused
//     into close. 3 launches.
// ---------------------------------------------------------------------------

#define W      2048
#define NPX    (W * W)
#define WORDS  64
#define NPAT   64
#define NB     8192
#define VLO    0.40f
#define VSC    40960.0f      // NB / 0.2
#define CAP    512

__device__ float g_B[NPX];
__device__ float g_vd[NPAT];
__device__ float g_vu[NPAT];

// ---------------------------------------------------------------------------
__device__ __forceinline__ int bin_of(float v) {
    float f = (v - VLO) * VSC;
    int b = (int)floorf(f);
    return b < 0 ? 0 : (b > NB - 1 ? NB - 1 : b);
}

// ---------------------------------------------------------------------------
// K1: fused 9x9 separable box blur. Tile 64x32 out, halo 4. 256 threads.
__global__ void k_blur(const float* __restrict__ x,
                       const float* __restrict__ kptr) {
    __shared__ float raw[40][72];
    __shared__ float hs[40][64];
    int c0 = blockIdx.x << 6;
    int r0 = blockIdx.y << 5;
    int tid = threadIdx.x;
    float kf = __ldg(kptr);

    for (int i = tid; i < 40 * 72; i += 256) {
        int rr = i / 72, cc = i % 72;
        int gr = r0 - 4 + rr, gc = c0 - 4 + cc;
        float v = 0.0f;
        if (gr >= 0 && gr < W && gc >= 0 && gc < W) v = x[(gr << 11) + gc];
        raw[rr][cc] = v;
    }
    __syncthreads();

    for (int i = tid; i < 40 * 64; i += 256) {
        int rr = i >> 6, cc = i & 63;
        float s = 0.0f;
#pragma unroll
        for (int k = 0; k < 9; ++k) s += raw[rr][cc + k];
        hs[rr][cc] = s;
    }
    __syncthreads();

    for (int i = tid; i < 32 * 64; i += 256) {
        int orow = i >> 6, oc = i & 63;
        float s = 0.0f;
#pragma unroll
        for (int k = 0; k < 9; ++k) s += hs[orow + k][oc];
        int gr = r0 + orow, gc = c0 + oc;
        g_B[(gr << 11) + gc] = s * kf;
    }
}

// ---------------------------------------------------------------------------
__device__ float kth_largest(const float* a, int n, int k) {
    if (n <= 0) return 0.5f;
    if (k >= n) k = n - 1;
    for (int i = 0; i < n; ++i) {
        float v = a[i];
        int g = 0, e = 0;
        for (int j = 0; j < n; ++j) {
            if (a[j] > v) g++;
            else if (a[j] == v) e++;
        }
        if (g <= k && k < g + e) return v;
    }
    return a[0];
}

// K2: per-patch order statistics via SHARED histogram. 64 blocks x 1024 thr.
__global__ void k_select() {
    int p = blockIdx.x;
    int t = threadIdx.x;
    int lane = t & 31, wid = t >> 5;

    __shared__ unsigned hist[NB];          // 32 KB
    __shared__ unsigned warpSuf[32];
    __shared__ int s_binD, s_rD, s_binU, s_rU;
    __shared__ float listD[CAP];
    __shared__ float listU[CAP];
    __shared__ int cntD, cntU;

#pragma unroll
    for (int i = 0; i < NB / 1024; ++i) hist[t + i * 1024] = 0u;
    if (t == 0) { cntD = 0; cntU = 0; }
    __syncthreads();

    int pr = (p >> 3) << 8, pc = (p & 7) << 8;
    const float4* B4 = (const float4*)g_B;

    // pass 1: build histogram (shared atomics, low conflict degree)
    for (int i = t; i < 16384; i += 1024) {
        int rr = pr + (i >> 6);
        int cc = pc + ((i & 63) << 2);
        float4 v = B4[((rr << 11) + cc) >> 2];
        atomicAdd(&hist[bin_of(v.x)], 1u);
        atomicAdd(&hist[bin_of(v.y)], 1u);
        atomicAdd(&hist[bin_of(v.z)], 1u);
        atomicAdd(&hist[bin_of(v.w)], 1u);
    }
    __syncthreads();

    // segment sums: 8 bins per thread
    unsigned segv = 0;
#pragma unroll
    for (int b = 0; b < 8; ++b) segv += hist[t * 8 + b];

    // warp-level inclusive suffix sum
    unsigned suf = segv;
#pragma unroll
    for (int off = 1; off < 32; off <<= 1) {
        unsigned v = __shfl_down_sync(0xFFFFFFFFu, suf, off);
        if (lane + off < 32) suf += v;
    }
    unsigned wtot = __shfl_sync(0xFFFFFFFFu, suf, 0);
    if (lane == 0) warpSuf[wid] = wtot;
    __syncthreads();
    if (wid == 0) {
        unsigned tot = warpSuf[lane];
        unsigned ss = tot;
#pragma unroll
        for (int off = 1; off < 32; off <<= 1) {
            unsigned v = __shfl_down_sync(0xFFFFFFFFu, ss, off);
            if (lane + off < 32) ss += v;
        }
        warpSuf[lane] = ss - tot;          // exclusive suffix of warp totals
    }
    __syncthreads();

    unsigned incl = suf + warpSuf[wid];
    unsigned above = incl - segv;

    bool frame = (p < 8) || (p >= 56) || ((p & 7) == 0) || ((p & 7) == 7);
    float lo = frame ? (0.47f - 0.05f) : 0.47f;
    float hiT = 0.43f;
    const float inv = 1.0f / 65536.0f;
    int Clo = (int)ceilf(lo * 65536.0f);
    while ((float)Clo * inv < lo) Clo++;
    while (Clo > 0 && (float)(Clo - 1) * inv >= lo) Clo--;
    int Chi = (int)floorf(hiT * 65536.0f);
    while ((float)(Chi + 1) * inv <= hiT) Chi++;
    while (Chi > 0 && (float)Chi * inv > hiT) Chi--;
    int kd = Clo - 1;
    int ku = Chi;

    if ((unsigned)kd >= above && (unsigned)kd < incl) {
        unsigned S = above;
        for (int b = 7; b >= 0; --b) {
            unsigned hb = hist[t * 8 + b];
            if ((unsigned)kd < S + hb) { s_binD = t * 8 + b; s_rD = (int)((unsigned)kd - S); break; }
            S += hb;
        }
    }
    if ((unsigned)ku >= above && (unsigned)ku < incl) {
        unsigned S = above;
        for (int b = 7; b >= 0; --b) {
            unsigned hb = hist[t * 8 + b];
            if ((unsigned)ku < S + hb) { s_binU = t * 8 + b; s_rU = (int)((unsigned)ku - S); break; }
            S += hb;
        }
    }
    __syncthreads();

    // pass 2: collect candidate values of the two bins (L2-resident reads)
    int binD = s_binD, binU = s_binU;
    for (int i = t; i < 16384; i += 1024) {
        int rr = pr + (i >> 6);
        int cc = pc + ((i & 63) << 2);
        float4 v = B4[((rr << 11) + cc) >> 2];
        float vv[4] = {v.x, v.y, v.z, v.w};
#pragma unroll
        for (int q = 0; q < 4; ++q) {
            int b = bin_of(vv[q]);
            if (b == binD) {
                int pos = atomicAdd(&cntD, 1);
                if (pos < CAP) listD[pos] = vv[q];
            }
            if (binU != binD && b == binU) {
                int pos = atomicAdd(&cntU, 1);
                if (pos < CAP) listU[pos] = vv[q];
            }
        }
    }
    __syncthreads();

    if (t == 0) {
        int nD = cntD < CAP ? cntD : CAP;
        g_vd[p] = kth_largest(listD, nD, s_rD);
        if (binU == binD) {
            g_vu[p] = kth_largest(listD, nD, s_rU);
        } else {
            int nU = cntU < CAP ? cntU : CAP;
            g_vu[p] = kth_largest(listU, nU, s_rU);
        }
    }
}

// ---------------------------------------------------------------------------
// K3: fused close: inline threshold iteration + binarize + dilH + dilV +
//     eroH + eroV + f32 expand.
// Grid (8, 64) = 512 blocks: tile 256 cols x 32 rows. 256 threads.
// bin tile: rows r0-8..r0+39 (48), words wbase-2..wbase+9 (12)
__global__ void k_close(float* __restrict__ out) {
    __shared__ unsigned sbin[48][12];
    __shared__ unsigned sdh[48][12];   // dilH: word j = global wbase-1+j, j=0..9
    __shared__ unsigned sdv[40][12];   // dilV: row dr = global r0-4+dr
    __shared__ unsigned seh[40][8];    // eroH
    __shared__ unsigned sfw[32][8];    // final words
    __shared__ float svd[NPAT], svu[NPAT];
    __shared__ float sth[NPAT];
    int wbase = blockIdx.x << 3;
    int r0 = blockIdx.y << 5;
    int tid = threadIdx.x;
    int warpId = tid >> 5, lane = tid & 31;

    // parallel load of vd/vu, then thread 0 runs the exact ulp iteration
    if (tid < NPAT) { svd[tid] = g_vd[tid]; svu[tid] = g_vu[tid]; }
    __syncthreads();
    if (tid == 0) {
        float t = 0.5f;
        for (int p = 0; p < NPAT; ++p) {
            float vd = svd[p], vu = svu[p];
            int guard = 0;
            while (t >= vd && guard < 1000000) {
                guard++;
                bool jumped = false;
                if (t >= 0.25f && t < 1.0f) {
                    float bandlo = (t >= 0.5f) ? 0.5f : 0.25f;
                    int ulps     = (t >= 0.5f) ? 839 : 1678;
                    float tgt = fmaxf(vd, bandlo);
                    int mt = __float_as_int(t), mv = __float_as_int(tgt);
                    int kj = (mt - mv) / ulps - 1;
                    if (kj > 0) { t = __int_as_float(mt - kj * ulps); jumped = true; }
                }
                if (!jumped) t = t - 5e-5f;
            }
            guard = 0;
            while (t < vu && guard < 2000000) {
                guard++;
                bool jumped = false;
                if (t >= 0.25f && t < 1.0f) {
                    float bandhi = (t >= 0.5f) ? 1.0f : 0.5f;
                    int ulps     = (t >= 0.5f) ? 84 : 168;
                    float tgt = fminf(vu, bandhi);
                    int mt = __float_as_int(t), mv = __float_as_int(tgt);
                    int kj = (mv - mt) / ulps - 1;
                    if (kj > 0) { t = __int_as_float(mt + kj * ulps); jumped = true; }
                }
                if (!jumped) t = t + 5e-6f;
            }
            sth[p] = t;
        }
    }
    __syncthreads();

    // binarize 48 rows x 12 words: warp task = 4 words of one row (float4/lane)
#pragma unroll 2
    for (int tsk = warpId; tsk < 48 * 3; tsk += 8) {
        int row = tsk / 3, qw = tsk - row * 3;
        int tw = (qw << 2) + (lane >> 3);        // 0..11
        int gw = wbase - 2 + tw;
        int gr = r0 - 8 + row;
        unsigned nib = 0;
        if (gr >= 0 && gr < W && gw >= 0 && gw < WORDS) {
            float th = sth[((gr >> 8) << 3) | (gw >> 3)];
            const float4* rp = (const float4*)(g_B + (gr << 11));
            float4 v = rp[(gw << 3) + (lane & 7)];
            nib = (unsigned)(v.x > th) | ((unsigned)(v.y > th) << 1)
                | ((unsigned)(v.z > th) << 2) | ((unsigned)(v.w > th) << 3);
        }
        unsigned x = nib | (__shfl_xor_sync(0xFFFFFFFFu, nib, 1) << 4);
        x = x | (__shfl_xor_sync(0xFFFFFFFFu, x, 2) << 8);
        x = x | (__shfl_xor_sync(0xFFFFFFFFu, x, 4) << 16);
        if ((lane & 7) == 0) sbin[row][tw] = x;
    }
    __syncthreads();

    // horizontal dilate (pad 0): j = 0..9 (global word wbase-1+j)
    for (int i = tid; i < 48 * 10; i += 256) {
        int row = i / 10, j = i - row * 10;
        unsigned curw = sbin[row][j + 1];
        unsigned left = sbin[row][j];
        unsigned right = sbin[row][j + 2];
        unsigned long long a = ((unsigned long long)curw << 32) | left;
        unsigned long long b = ((unsigned long long)right << 32) | curw;
        unsigned o = curw;
#pragma unroll
        for (int k = 1; k <= 4; ++k) {
            o |= (unsigned)(a >> (32 - k));
            o |= (unsigned)(b >> k);
        }
        sdh[row][j] = o;
    }
    __syncthreads();

    // vertical dilate (pad 0): dr = 0..39 (global row r0-4+dr)
    for (int i = tid; i < 40 * 10; i += 256) {
        int dr = i / 10, j = i - dr * 10;
        unsigned o = 0u;
#pragma unroll
        for (int k = 0; k < 9; ++k) o |= sdh[dr + k][j];
        sdv[dr][j] = o;
    }
    __syncthreads();

    // horizontal erode (pad 1 outside image): out word ow (global wbase+ow)
    for (int i = tid; i < 40 * 8; i += 256) {
        int dr = i >> 3, ow = i & 7;
        unsigned curw = sdv[dr][ow + 1];
        unsigned left  = (wbase + ow - 1 >= 0)    ? sdv[dr][ow]     : 0xFFFFFFFFu;
        unsigned right = (wbase + ow + 1 < WORDS) ? sdv[dr][ow + 2] : 0xFFFFFFFFu;
        unsigned long long a = ((unsigned long long)curw << 32) | left;
        unsigned long long b = ((unsigned long long)right << 32) | curw;
        unsigned o = curw;
#pragma unroll
        for (int k = 1; k <= 4; ++k) {
            o &= (unsigned)(a >> (32 - k));
            o &= (unsigned)(b >> k);
        }
        seh[dr][ow] = o;
    }
    __syncthreads();

    // vertical erode (pad 1 outside image): out rows 0..31
    for (int i = tid; i < 32 * 8; i += 256) {
        int orow = i >> 3, ow = i & 7;
        unsigned o = 0xFFFFFFFFu;
#pragma unroll
        for (int k = 0; k < 9; ++k) {
            int gr = r0 + orow - 4 + k;
            unsigned v = (gr >= 0 && gr < W) ? seh[orow + k][ow] : 0xFFFFFFFFu;
            o &= v;
        }
        sfw[orow][ow] = o;
    }
    __syncthreads();

    // expand to f32, float4 stores (32 rows x 64 quads)
    float4* out4 = (float4*)out;
    for (int i = tid; i < 32 * 64; i += 256) {
        int orow = i >> 6;
        int c = (i & 63) << 2;
        unsigned wv = sfw[orow][c >> 5];
        int sh = c & 31;
        float4 o;
        o.x = ((wv >> (sh + 0)) & 1u) ? 1.0f : 0.0f;
        o.y = ((wv >> (sh + 1)) & 1u) ? 1.0f : 0.0f;
        o.z = ((wv >> (sh + 2)) & 1u) ? 1.0f : 0.0f;
        o.w = ((wv >> (sh + 3)) & 1u) ? 1.0f : 0.0f;
        out4[(((r0 + orow) << 11) + (wbase << 5) + c) >> 2] = o;
    }
}

// ---------------------------------------------------------------------------
extern "C" void kernel_launch(void* const* d_in, const int* in_sizes, int n_in,
                              void* d_out, int out_size) {
    const float* x  = (const float*)d_in[0];
    const float* bk = (const float*)d_in[1];
    float* out = (float*)d_out;

    dim3 gblur(W / 64, W / 32);
    k_blur<<<gblur, 256>>>(x, bk);
    k_select<<<NPAT, 1024>>>();
    dim3 gclose(8, W / 32);
    k_close<<<gclose, 256>>>(out);
}

// round 9
// speedup vs baseline: 1.2146x; 1.0600x over previous
#include <cuda_runtime.h>
#include <stdint.h>

// ---------------------------------------------------------------------------
// BlurModel: 9x9 box blur -> per-patch sequential threshold search ->
// binarize -> morphological close, 2048x2048 f32.
// R9 (= R8 resubmit after infra failure): blur register-blocked
// (float4 LDS, ~3.5x less shared traffic); select/close as R7. 3 launches.
// ---------------------------------------------------------------------------

#define W      2048
#define NPX    (W * W)
#define WORDS  64
#define NPAT   64
#define NB     8192
#define VLO    0.40f
#define VSC    40960.0f      // NB / 0.2
#define CAP    512

__device__ float g_B[NPX];
__device__ float g_vd[NPAT];
__device__ float g_vu[NPAT];

// ---------------------------------------------------------------------------
__device__ __forceinline__ int bin_of(float v) {
    float f = (v - VLO) * VSC;
    int b = (int)floorf(f);
    return b < 0 ? 0 : (b > NB - 1 ? NB - 1 : b);
}

// ---------------------------------------------------------------------------
// K1: fused 9x9 separable box blur, register-blocked.
// Tile 64x32 out, halo 4. 256 threads.
__global__ void k_blur(const float* __restrict__ x,
                       const float* __restrict__ kptr) {
    __shared__ __align__(16) float raw[40][72];
    __shared__ __align__(16) float hs[40][64];
    int c0 = blockIdx.x << 6;
    int r0 = blockIdx.y << 5;
    int tid = threadIdx.x;
    float kf = __ldg(kptr);

    // load raw tile (40 x 72) with zero padding
    for (int i = tid; i < 40 * 72; i += 256) {
        int rr = i / 72, cc = i - rr * 72;
        int gr = r0 - 4 + rr, gc = c0 - 4 + cc;
        float v = 0.0f;
        if (gr >= 0 && gr < W && gc >= 0 && gc < W) v = x[(gr << 11) + gc];
        raw[rr][cc] = v;
    }
    __syncthreads();

    // horizontal 9-sum: each task = 4 adjacent outputs of one row.
    // window raw[row][c .. c+11] as 3 aligned float4 loads; ascending adds.
    for (int i = tid; i < 40 * 16; i += 256) {
        int row = i >> 4, g = i & 15;
        int c = g << 2;
        const float4* rp = (const float4*)&raw[row][c];
        float4 a = rp[0], b = rp[1], d = rp[2];
        float f0 = a.x, f1 = a.y, f2 = a.z, f3 = a.w;
        float f4 = b.x, f5 = b.y, f6 = b.z, f7 = b.w;
        float f8 = d.x, f9 = d.y, f10 = d.z, f11 = d.w;
        float4 o;
        o.x = ((((((((f0 + f1) + f2) + f3) + f4) + f5) + f6) + f7) + f8);
        o.y = ((((((((f1 + f2) + f3) + f4) + f5) + f6) + f7) + f8) + f9);
        o.z = ((((((((f2 + f3) + f4) + f5) + f6) + f7) + f8) + f9) + f10);
        o.w = ((((((((f3 + f4) + f5) + f6) + f7) + f8) + f9) + f10) + f11);
        *(float4*)&hs[row][c] = o;
    }
    __syncthreads();

    // vertical 9-sum: thread = 8 consecutive output rows of one column.
    // loads hs rows once (16 scalar LDS), sums registers in ascending order.
    {
        int oc = tid & 63;
        int rg = tid >> 6;            // 0..3
        int base = rg << 3;           // first output row of this thread
        float h[16];
#pragma unroll
        for (int k = 0; k < 16; ++k) h[k] = hs[base + k][oc];
        int gc = c0 + oc;
#pragma unroll
        for (int j = 0; j < 8; ++j) {
            float s = h[j];
#pragma unroll
            for (int k = 1; k < 9; ++k) s += h[j + k];
            int gr = r0 + base + j;
            g_B[(gr << 11) + gc] = s * kf;
        }
    }
}

// ---------------------------------------------------------------------------
__device__ float kth_largest(const float* a, int n, int k) {
    if (n <= 0) return 0.5f;
    if (k >= n) k = n - 1;
    for (int i = 0; i < n; ++i) {
        float v = a[i];
        int g = 0, e = 0;
        for (int j = 0; j < n; ++j) {
            if (a[j] > v) g++;
            else if (a[j] == v) e++;
        }
        if (g <= k && k < g + e) return v;
    }
    return a[0];
}

// K2: per-patch order statistics via SHARED histogram. 64 blocks x 1024 thr.
__global__ void k_select() {
    int p = blockIdx.x;
    int t = threadIdx.x;
    int lane = t & 31, wid = t >> 5;

    __shared__ unsigned hist[NB];          // 32 KB
    __shared__ unsigned warpSuf[32];
    __shared__ int s_binD, s_rD, s_binU, s_rU;
    __shared__ float listD[CAP];
    __shared__ float listU[CAP];
    __shared__ int cntD, cntU;

#pragma unroll
    for (int i = 0; i < NB / 1024; ++i) hist[t + i * 1024] = 0u;
    if (t == 0) { cntD = 0; cntU = 0; }
    __syncthreads();

    int pr = (p >> 3) << 8, pc = (p & 7) << 8;
    const float4* B4 = (const float4*)g_B;

    // pass 1: build histogram (shared atomics, low conflict degree)
    for (int i = t; i < 16384; i += 1024) {
        int rr = pr + (i >> 6);
        int cc = pc + ((i & 63) << 2);
        float4 v = B4[((rr << 11) + cc) >> 2];
        atomicAdd(&hist[bin_of(v.x)], 1u);
        atomicAdd(&hist[bin_of(v.y)], 1u);
        atomicAdd(&hist[bin_of(v.z)], 1u);
        atomicAdd(&hist[bin_of(v.w)], 1u);
    }
    __syncthreads();

    // segment sums: 8 bins per thread
    unsigned segv = 0;
#pragma unroll
    for (int b = 0; b < 8; ++b) segv += hist[t * 8 + b];

    // warp-level inclusive suffix sum
    unsigned suf = segv;
#pragma unroll
    for (int off = 1; off < 32; off <<= 1) {
        unsigned v = __shfl_down_sync(0xFFFFFFFFu, suf, off);
        if (lane + off < 32) suf += v;
    }
    unsigned wtot = __shfl_sync(0xFFFFFFFFu, suf, 0);
    if (lane == 0) warpSuf[wid] = wtot;
    __syncthreads();
    if (wid == 0) {
        unsigned tot = warpSuf[lane];
        unsigned ss = tot;
#pragma unroll
        for (int off = 1; off < 32; off <<= 1) {
            unsigned v = __shfl_down_sync(0xFFFFFFFFu, ss, off);
            if (lane + off < 32) ss += v;
        }
        warpSuf[lane] = ss - tot;          // exclusive suffix of warp totals
    }
    __syncthreads();

    unsigned incl = suf + warpSuf[wid];
    unsigned above = incl - segv;

    bool frame = (p < 8) || (p >= 56) || ((p & 7) == 0) || ((p & 7) == 7);
    float lo = frame ? (0.47f - 0.05f) : 0.47f;
    float hiT = 0.43f;
    const float inv = 1.0f / 65536.0f;
    int Clo = (int)ceilf(lo * 65536.0f);
    while ((float)Clo * inv < lo) Clo++;
    while (Clo > 0 && (float)(Clo - 1) * inv >= lo) Clo--;
    int Chi = (int)floorf(hiT * 65536.0f);
    while ((float)(Chi + 1) * inv <= hiT) Chi++;
    while (Chi > 0 && (float)Chi * inv > hiT) Chi--;
    int kd = Clo - 1;
    int ku = Chi;

    if ((unsigned)kd >= above && (unsigned)kd < incl) {
        unsigned S = above;
        for (int b = 7; b >= 0; --b) {
            unsigned hb = hist[t * 8 + b];
            if ((unsigned)kd < S + hb) { s_binD = t * 8 + b; s_rD = (int)((unsigned)kd - S); break; }
            S += hb;
        }
    }
    if ((unsigned)ku >= above && (unsigned)ku < incl) {
        unsigned S = above;
        for (int b = 7; b >= 0; --b) {
            unsigned hb = hist[t * 8 + b];
            if ((unsigned)ku < S + hb) { s_binU = t * 8 + b; s_rU = (int)((unsigned)ku - S); break; }
            S += hb;
        }
    }
    __syncthreads();

    // pass 2: collect candidate values of the two bins (L2-resident reads)
    int binD = s_binD, binU = s_binU;
    for (int i = t; i < 16384; i += 1024) {
        int rr = pr + (i >> 6);
        int cc = pc + ((i & 63) << 2);
        float4 v = B4[((rr << 11) + cc) >> 2];
        float vv[4] = {v.x, v.y, v.z, v.w};
#pragma unroll
        for (int q = 0; q < 4; ++q) {
            int b = bin_of(vv[q]);
            if (b == binD) {
                int pos = atomicAdd(&cntD, 1);
                if (pos < CAP) listD[pos] = vv[q];
            }
            if (binU != binD && b == binU) {
                int pos = atomicAdd(&cntU, 1);
                if (pos < CAP) listU[pos] = vv[q];
            }
        }
    }
    __syncthreads();

    if (t == 0) {
        int nD = cntD < CAP ? cntD : CAP;
        g_vd[p] = kth_largest(listD, nD, s_rD);
        if (binU == binD) {
            g_vu[p] = kth_largest(listD, nD, s_rU);
        } else {
            int nU = cntU < CAP ? cntU : CAP;
            g_vu[p] = kth_largest(listU, nU, s_rU);
        }
    }
}

// ---------------------------------------------------------------------------
// K3: fused close: inline threshold iteration + binarize + dilH + dilV +
//     eroH + eroV + f32 expand.
// Grid (8, 64) = 512 blocks: tile 256 cols x 32 rows. 256 threads.
__global__ void k_close(float* __restrict__ out) {
    __shared__ unsigned sbin[48][12];
    __shared__ unsigned sdh[48][12];
    __shared__ unsigned sdv[40][12];
    __shared__ unsigned seh[40][8];
    __shared__ unsigned sfw[32][8];
    __shared__ float svd[NPAT], svu[NPAT];
    __shared__ float sth[NPAT];
    int wbase = blockIdx.x << 3;
    int r0 = blockIdx.y << 5;
    int tid = threadIdx.x;
    int warpId = tid >> 5, lane = tid & 31;

    if (tid < NPAT) { svd[tid] = g_vd[tid]; svu[tid] = g_vu[tid]; }
    __syncthreads();
    if (tid == 0) {
        float t = 0.5f;
        for (int p = 0; p < NPAT; ++p) {
            float vd = svd[p], vu = svu[p];
            int guard = 0;
            while (t >= vd && guard < 1000000) {
                guard++;
                bool jumped = false;
                if (t >= 0.25f && t < 1.0f) {
                    float bandlo = (t >= 0.5f) ? 0.5f : 0.25f;
                    int ulps     = (t >= 0.5f) ? 839 : 1678;
                    float tgt = fmaxf(vd, bandlo);
                    int mt = __float_as_int(t), mv = __float_as_int(tgt);
                    int kj = (mt - mv) / ulps - 1;
                    if (kj > 0) { t = __int_as_float(mt - kj * ulps); jumped = true; }
                }
                if (!jumped) t = t - 5e-5f;
            }
            guard = 0;
            while (t < vu && guard < 2000000) {
                guard++;
                bool jumped = false;
                if (t >= 0.25f && t < 1.0f) {
                    float bandhi = (t >= 0.5f) ? 1.0f : 0.5f;
                    int ulps     = (t >= 0.5f) ? 84 : 168;
                    float tgt = fminf(vu, bandhi);
                    int mt = __float_as_int(t), mv = __float_as_int(tgt);
                    int kj = (mv - mt) / ulps - 1;
                    if (kj > 0) { t = __int_as_float(mt + kj * ulps); jumped = true; }
                }
                if (!jumped) t = t + 5e-6f;
            }
            sth[p] = t;
        }
    }
    __syncthreads();

    // binarize 48 rows x 12 words
#pragma unroll 2
    for (int tsk = warpId; tsk < 48 * 3; tsk += 8) {
        int row = tsk / 3, qw = tsk - row * 3;
        int tw = (qw << 2) + (lane >> 3);
        int gw = wbase - 2 + tw;
        int gr = r0 - 8 + row;
        unsigned nib = 0;
        if (gr >= 0 && gr < W && gw >= 0 && gw < WORDS) {
            float th = sth[((gr >> 8) << 3) | (gw >> 3)];
            const float4* rp = (const float4*)(g_B + (gr << 11));
            float4 v = rp[(gw << 3) + (lane & 7)];
            nib = (unsigned)(v.x > th) | ((unsigned)(v.y > th) << 1)
                | ((unsigned)(v.z > th) << 2) | ((unsigned)(v.w > th) << 3);
        }
        unsigned x = nib | (__shfl_xor_sync(0xFFFFFFFFu, nib, 1) << 4);
        x = x | (__shfl_xor_sync(0xFFFFFFFFu, x, 2) << 8);
        x = x | (__shfl_xor_sync(0xFFFFFFFFu, x, 4) << 16);
        if ((lane & 7) == 0) sbin[row][tw] = x;
    }
    __syncthreads();

    // horizontal dilate (pad 0): j = 0..9
    for (int i = tid; i < 48 * 10; i += 256) {
        int row = i / 10, j = i - row * 10;
        unsigned curw = sbin[row][j + 1];
        unsigned left = sbin[row][j];
        unsigned right = sbin[row][j + 2];
        unsigned long long a = ((unsigned long long)curw << 32) | left;
        unsigned long long b = ((unsigned long long)right << 32) | curw;
        unsigned o = curw;
#pragma unroll
        for (int k = 1; k <= 4; ++k) {
            o |= (unsigned)(a >> (32 - k));
            o |= (unsigned)(b >> k);
        }
        sdh[row][j] = o;
    }
    __syncthreads();

    // vertical dilate (pad 0): dr = 0..39
    for (int i = tid; i < 40 * 10; i += 256) {
        int dr = i / 10, j = i - dr * 10;
        unsigned o = 0u;
#pragma unroll
        for (int k = 0; k < 9; ++k) o |= sdh[dr + k][j];
        sdv[dr][j] = o;
    }
    __syncthreads();

    // horizontal erode (pad 1 outside image)
    for (int i = tid; i < 40 * 8; i += 256) {
        int dr = i >> 3, ow = i & 7;
        unsigned curw = sdv[dr][ow + 1];
        unsigned left  = (wbase + ow - 1 >= 0)    ? sdv[dr][ow]     : 0xFFFFFFFFu;
        unsigned right = (wbase + ow + 1 < WORDS) ? sdv[dr][ow + 2] : 0xFFFFFFFFu;
        unsigned long long a = ((unsigned long long)curw << 32) | left;
        unsigned long long b = ((unsigned long long)right << 32) | curw;
        unsigned o = curw;
#pragma unroll
        for (int k = 1; k <= 4; ++k) {
            o &= (unsigned)(a >> (32 - k));
            o &= (unsigned)(b >> k);
        }
        seh[dr][ow] = o;
    }
    __syncthreads();

    // vertical erode (pad 1 outside image)
    for (int i = tid; i < 32 * 8; i += 256) {
        int orow = i >> 3, ow = i & 7;
        unsigned o = 0xFFFFFFFFu;
#pragma unroll
        for (int k = 0; k < 9; ++k) {
            int gr = r0 + orow - 4 + k;
            unsigned v = (gr >= 0 && gr < W) ? seh[orow + k][ow] : 0xFFFFFFFFu;
            o &= v;
        }
        sfw[orow][ow] = o;
    }
    __syncthreads();

    // expand to f32, float4 stores
    float4* out4 = (float4*)out;
    for (int i = tid; i < 32 * 64; i += 256) {
        int orow = i >> 6;
        int c = (i & 63) << 2;
        unsigned wv = sfw[orow][c >> 5];
        int sh = c & 31;
        float4 o;
        o.x = ((wv >> (sh + 0)) & 1u) ? 1.0f : 0.0f;
        o.y = ((wv >> (sh + 1)) & 1u) ? 1.0f : 0.0f;
        o.z = ((wv >> (sh + 2)) & 1u) ? 1.0f : 0.0f;
        o.w = ((wv >> (sh + 3)) & 1u) ? 1.0f : 0.0f;
        out4[(((r0 + orow) << 11) + (wbase << 5) + c) >> 2] = o;
    }
}

// ---------------------------------------------------------------------------
extern "C" void kernel_launch(void* const* d_in, const int* in_sizes, int n_in,
                              void* d_out, int out_size) {
    const float* x  = (const float*)d_in[0];
    const float* bk = (const float*)d_in[1];
    float* out = (float*)d_out;

    dim3 gblur(W / 64, W / 32);
    k_blur<<<gblur, 256>>>(x, bk);
    k_select<<<NPAT, 1024>>>();
    dim3 gclose(8, W / 32);
    k_close<<<gclose, 256>>>(out);
}

// round 10
// speedup vs baseline: 1.2201x; 1.0045x over previous
#include <cuda_runtime.h>
#include <stdint.h>

// ---------------------------------------------------------------------------
// BlurModel: 9x9 box blur -> per-patch sequential threshold search ->
// binarize -> morphological close, 2048x2048 f32.
// R10: select split 2 blocks/patch with last-arriver finish (128-block
//      histogram build, global merge); blur zeroes hist; blur/close as R9.
// ---------------------------------------------------------------------------

#define W      2048
#define NPX    (W * W)
#define WORDS  64
#define NPAT   64
#define NB     8192
#define VLO    0.40f
#define VSC    40960.0f      // NB / 0.2
#define CAP    512

__device__ float    g_B[NPX];
__device__ unsigned g_hist[NPAT * NB];
__device__ int      g_done[NPAT];
__device__ float    g_vd[NPAT];
__device__ float    g_vu[NPAT];

// ---------------------------------------------------------------------------
__device__ __forceinline__ int bin_of(float v) {
    float f = (v - VLO) * VSC;
    int b = (int)floorf(f);
    return b < 0 ? 0 : (b > NB - 1 ? NB - 1 : b);
}

// ---------------------------------------------------------------------------
// K1: fused 9x9 separable box blur, register-blocked. Also zeroes the
// global histogram + done counters (graph-replay deterministic).
// Tile 64x32 out, halo 4. 256 threads, 2048 blocks.
__global__ void k_blur(const float* __restrict__ x,
                       const float* __restrict__ kptr) {
    __shared__ __align__(16) float raw[40][72];
    __shared__ __align__(16) float hs[40][64];
    int c0 = blockIdx.x << 6;
    int r0 = blockIdx.y << 5;
    int bid = blockIdx.y * gridDim.x + blockIdx.x;
    int tid = threadIdx.x;
    float kf = __ldg(kptr);

    // zero this block's slice of g_hist (2048 blocks x 256 u32 = 2 MB)
    {
        unsigned* hz = g_hist + bid * 256;
        if (tid < 64) ((uint4*)hz)[tid] = make_uint4(0, 0, 0, 0);
        if (bid == 0 && tid < NPAT) g_done[tid] = 0;
    }

    // load raw tile (40 x 72) with zero padding
    for (int i = tid; i < 40 * 72; i += 256) {
        int rr = i / 72, cc = i - rr * 72;
        int gr = r0 - 4 + rr, gc = c0 - 4 + cc;
        float v = 0.0f;
        if (gr >= 0 && gr < W && gc >= 0 && gc < W) v = x[(gr << 11) + gc];
        raw[rr][cc] = v;
    }
    __syncthreads();

    // horizontal 9-sum: each task = 4 adjacent outputs of one row.
    for (int i = tid; i < 40 * 16; i += 256) {
        int row = i >> 4, g = i & 15;
        int c = g << 2;
        const float4* rp = (const float4*)&raw[row][c];
        float4 a = rp[0], b = rp[1], d = rp[2];
        float f0 = a.x, f1 = a.y, f2 = a.z, f3 = a.w;
        float f4 = b.x, f5 = b.y, f6 = b.z, f7 = b.w;
        float f8 = d.x, f9 = d.y, f10 = d.z, f11 = d.w;
        float4 o;
        o.x = ((((((((f0 + f1) + f2) + f3) + f4) + f5) + f6) + f7) + f8);
        o.y = ((((((((f1 + f2) + f3) + f4) + f5) + f6) + f7) + f8) + f9);
        o.z = ((((((((f2 + f3) + f4) + f5) + f6) + f7) + f8) + f9) + f10);
        o.w = ((((((((f3 + f4) + f5) + f6) + f7) + f8) + f9) + f10) + f11);
        *(float4*)&hs[row][c] = o;
    }
    __syncthreads();

    // vertical 9-sum: thread = 8 consecutive output rows of one column.
    {
        int oc = tid & 63;
        int rg = tid >> 6;
        int base = rg << 3;
        float h[16];
#pragma unroll
        for (int k = 0; k < 16; ++k) h[k] = hs[base + k][oc];
        int gc = c0 + oc;
#pragma unroll
        for (int j = 0; j < 8; ++j) {
            float s = h[j];
#pragma unroll
            for (int k = 1; k < 9; ++k) s += h[j + k];
            int gr = r0 + base + j;
            g_B[(gr << 11) + gc] = s * kf;
        }
    }
}

// ---------------------------------------------------------------------------
__device__ float kth_largest(const float* a, int n, int k) {
    if (n <= 0) return 0.5f;
    if (k >= n) k = n - 1;
    for (int i = 0; i < n; ++i) {
        float v = a[i];
        int g = 0, e = 0;
        for (int j = 0; j < n; ++j) {
            if (a[j] > v) g++;
            else if (a[j] == v) e++;
        }
        if (g <= k && k < g + e) return v;
    }
    return a[0];
}

// K2: 128 blocks (2 per patch) x 1024 threads.
// Each block: smem hist of its half patch -> merge to global.
// Last arriver per patch: reload merged hist, rank, candidates, kth.
__global__ void k_select() {
    int blk = blockIdx.x;
    int p = blk >> 1;
    int half = blk & 1;
    int t = threadIdx.x;
    int lane = t & 31, wid = t >> 5;

    __shared__ unsigned hist[NB];          // 32 KB
    __shared__ unsigned warpSuf[32];
    __shared__ int s_binD, s_rD, s_binU, s_rU;
    __shared__ float listD[CAP];
    __shared__ float listU[CAP];
    __shared__ int cntD, cntU;
    __shared__ int sWho;

#pragma unroll
    for (int i = 0; i < NB / 1024; ++i) hist[t + i * 1024] = 0u;
    if (t == 0) { cntD = 0; cntU = 0; }
    __syncthreads();

    int prh = (((p >> 3) << 8) + (half << 7));   // first row of this half
    int pc = (p & 7) << 8;
    const float4* B4 = (const float4*)g_B;

    // histogram of half patch: 128 rows x 256 cols = 8192 float4
    for (int i = t; i < 8192; i += 1024) {
        int rr = prh + (i >> 6);
        int cc = pc + ((i & 63) << 2);
        float4 v = B4[((rr << 11) + cc) >> 2];
        atomicAdd(&hist[bin_of(v.x)], 1u);
        atomicAdd(&hist[bin_of(v.y)], 1u);
        atomicAdd(&hist[bin_of(v.z)], 1u);
        atomicAdd(&hist[bin_of(v.w)], 1u);
    }
    __syncthreads();

    // merge to global per-patch hist (skip-zero, spread atomics)
    unsigned* gh = g_hist + p * NB;
#pragma unroll
    for (int i = 0; i < NB / 1024; ++i) {
        int idx = t + i * 1024;
        unsigned v = hist[idx];
        if (v) atomicAdd(&gh[idx], v);
    }
    __threadfence();
    __syncthreads();
    if (t == 0) sWho = atomicAdd(&g_done[p], 1);
    __syncthreads();
    if (sWho == 0) return;          // first finisher exits; last one proceeds
    __threadfence();

    // reload merged histogram (L2 loads, bypass L1)
    {
        const uint4* gh4 = (const uint4*)gh;
        uint4* s4 = (uint4*)hist;
#pragma unroll
        for (int i = 0; i < NB / 4 / 1024; ++i) {
            uint4 v = __ldcg(&gh4[t + i * 1024]);
            s4[t + i * 1024] = v;
        }
    }
    __syncthreads();

    // segment sums: 8 bins per thread
    unsigned segv = 0;
#pragma unroll
    for (int b = 0; b < 8; ++b) segv += hist[t * 8 + b];

    // warp-level inclusive suffix sum
    unsigned suf = segv;
#pragma unroll
    for (int off = 1; off < 32; off <<= 1) {
        unsigned v = __shfl_down_sync(0xFFFFFFFFu, suf, off);
        if (lane + off < 32) suf += v;
    }
    unsigned wtot = __shfl_sync(0xFFFFFFFFu, suf, 0);
    if (lane == 0) warpSuf[wid] = wtot;
    __syncthreads();
    if (wid == 0) {
        unsigned tot = warpSuf[lane];
        unsigned ss = tot;
#pragma unroll
        for (int off = 1; off < 32; off <<= 1) {
            unsigned v = __shfl_down_sync(0xFFFFFFFFu, ss, off);
            if (lane + off < 32) ss += v;
        }
        warpSuf[lane] = ss - tot;          // exclusive suffix of warp totals
    }
    __syncthreads();

    unsigned incl = suf + warpSuf[wid];
    unsigned above = incl - segv;

    bool frame = (p < 8) || (p >= 56) || ((p & 7) == 0) || ((p & 7) == 7);
    float lo = frame ? (0.47f - 0.05f) : 0.47f;
    float hiT = 0.43f;
    const float inv = 1.0f / 65536.0f;
    int Clo = (int)ceilf(lo * 65536.0f);
    while ((float)Clo * inv < lo) Clo++;
    while (Clo > 0 && (float)(Clo - 1) * inv >= lo) Clo--;
    int Chi = (int)floorf(hiT * 65536.0f);
    while ((float)(Chi + 1) * inv <= hiT) Chi++;
    while (Chi > 0 && (float)Chi * inv > hiT) Chi--;
    int kd = Clo - 1;
    int ku = Chi;

    if ((unsigned)kd >= above && (unsigned)kd < incl) {
        unsigned S = above;
        for (int b = 7; b >= 0; --b) {
            unsigned hb = hist[t * 8 + b];
            if ((unsigned)kd < S + hb) { s_binD = t * 8 + b; s_rD = (int)((unsigned)kd - S); break; }
            S += hb;
        }
    }
    if ((unsigned)ku >= above && (unsigned)ku < incl) {
        unsigned S = above;
        for (int b = 7; b >= 0; --b) {
            unsigned hb = hist[t * 8 + b];
            if ((unsigned)ku < S + hb) { s_binU = t * 8 + b; s_rU = (int)((unsigned)ku - S); break; }
            S += hb;
        }
    }
    __syncthreads();

    // candidate collection over FULL patch (L2-resident reads)
    int binD = s_binD, binU = s_binU;
    int pr = (p >> 3) << 8;
    for (int i = t; i < 16384; i += 1024) {
        int rr = pr + (i >> 6);
        int cc = pc + ((i & 63) << 2);
        float4 v = B4[((rr << 11) + cc) >> 2];
        float vv[4] = {v.x, v.y, v.z, v.w};
#pragma unroll
        for (int q = 0; q < 4; ++q) {
            int b = bin_of(vv[q]);
            if (b == binD) {
                int pos = atomicAdd(&cntD, 1);
                if (pos < CAP) listD[pos] = vv[q];
            }
            if (binU != binD && b == binU) {
                int pos = atomicAdd(&cntU, 1);
                if (pos < CAP) listU[pos] = vv[q];
            }
        }
    }
    __syncthreads();

    if (t == 0) {
        int nD = cntD < CAP ? cntD : CAP;
        g_vd[p] = kth_largest(listD, nD, s_rD);
        if (binU == binD) {
            g_vu[p] = kth_largest(listD, nD, s_rU);
        } else {
            int nU = cntU < CAP ? cntU : CAP;
            g_vu[p] = kth_largest(listU, nU, s_rU);
        }
    }
}

// ---------------------------------------------------------------------------
// K3: fused close: inline threshold iteration + binarize + dilH + dilV +
//     eroH + eroV + f32 expand.
// Grid (8, 64) = 512 blocks: tile 256 cols x 32 rows. 256 threads.
__global__ void k_close(float* __restrict__ out) {
    __shared__ unsigned sbin[48][12];
    __shared__ unsigned sdh[48][12];
    __shared__ unsigned sdv[40][12];
    __shared__ unsigned seh[40][8];
    __shared__ unsigned sfw[32][8];
    __shared__ float svd[NPAT], svu[NPAT];
    __shared__ float sth[NPAT];
    int wbase = blockIdx.x << 3;
    int r0 = blockIdx.y << 5;
    int tid = threadIdx.x;
    int warpId = tid >> 5, lane = tid & 31;

    if (tid < NPAT) { svd[tid] = g_vd[tid]; svu[tid] = g_vu[tid]; }
    __syncthreads();
    if (tid == 0) {
        float t = 0.5f;
        for (int p = 0; p < NPAT; ++p) {
            float vd = svd[p], vu = svu[p];
            int guard = 0;
            while (t >= vd && guard < 1000000) {
                guard++;
                bool jumped = false;
                if (t >= 0.25f && t < 1.0f) {
                    float bandlo = (t >= 0.5f) ? 0.5f : 0.25f;
                    int ulps     = (t >= 0.5f) ? 839 : 1678;
                    float tgt = fmaxf(vd, bandlo);
                    int mt = __float_as_int(t), mv = __float_as_int(tgt);
                    int kj = (mt - mv) / ulps - 1;
                    if (kj > 0) { t = __int_as_float(mt - kj * ulps); jumped = true; }
                }
                if (!jumped) t = t - 5e-5f;
            }
            guard = 0;
            while (t < vu && guard < 2000000) {
                guard++;
                bool jumped = false;
                if (t >= 0.25f && t < 1.0f) {
                    float bandhi = (t >= 0.5f) ? 1.0f : 0.5f;
                    int ulps     = (t >= 0.5f) ? 84 : 168;
                    float tgt = fminf(vu, bandhi);
                    int mt = __float_as_int(t), mv = __float_as_int(tgt);
                    int kj = (mv - mt) / ulps - 1;
                    if (kj > 0) { t = __int_as_float(mt + kj * ulps); jumped = true; }
                }
                if (!jumped) t = t + 5e-6f;
            }
            sth[p] = t;
        }
    }
    __syncthreads();

    // binarize 48 rows x 12 words
#pragma unroll 2
    for (int tsk = warpId; tsk < 48 * 3; tsk += 8) {
        int row = tsk / 3, qw = tsk - row * 3;
        int tw = (qw << 2) + (lane >> 3);
        int gw = wbase - 2 + tw;
        int gr = r0 - 8 + row;
        unsigned nib = 0;
        if (gr >= 0 && gr < W && gw >= 0 && gw < WORDS) {
            float th = sth[((gr >> 8) << 3) | (gw >> 3)];
            const float4* rp = (const float4*)(g_B + (gr << 11));
            float4 v = rp[(gw << 3) + (lane & 7)];
            nib = (unsigned)(v.x > th) | ((unsigned)(v.y > th) << 1)
                | ((unsigned)(v.z > th) << 2) | ((unsigned)(v.w > th) << 3);
        }
        unsigned x = nib | (__shfl_xor_sync(0xFFFFFFFFu, nib, 1) << 4);
        x = x | (__shfl_xor_sync(0xFFFFFFFFu, x, 2) << 8);
        x = x | (__shfl_xor_sync(0xFFFFFFFFu, x, 4) << 16);
        if ((lane & 7) == 0) sbin[row][tw] = x;
    }
    __syncthreads();

    // horizontal dilate (pad 0): j = 0..9
    for (int i = tid; i < 48 * 10; i += 256) {
        int row = i / 10, j = i - row * 10;
        unsigned curw = sbin[row][j + 1];
        unsigned left = sbin[row][j];
        unsigned right = sbin[row][j + 2];
        unsigned long long a = ((unsigned long long)curw << 32) | left;
        unsigned long long b = ((unsigned long long)right << 32) | curw;
        unsigned o = curw;
#pragma unroll
        for (int k = 1; k <= 4; ++k) {
            o |= (unsigned)(a >> (32 - k));
            o |= (unsigned)(b >> k);
        }
        sdh[row][j] = o;
    }
    __syncthreads();

    // vertical dilate (pad 0): dr = 0..39
    for (int i = tid; i < 40 * 10; i += 256) {
        int dr = i / 10, j = i - dr * 10;
        unsigned o = 0u;
#pragma unroll
        for (int k = 0; k < 9; ++k) o |= sdh[dr + k][j];
        sdv[dr][j] = o;
    }
    __syncthreads();

    // horizontal erode (pad 1 outside image)
    for (int i = tid; i < 40 * 8; i += 256) {
        int dr = i >> 3, ow = i & 7;
        unsigned curw = sdv[dr][ow + 1];
        unsigned left  = (wbase + ow - 1 >= 0)    ? sdv[dr][ow]     : 0xFFFFFFFFu;
        unsigned right = (wbase + ow + 1 < WORDS) ? sdv[dr][ow + 2] : 0xFFFFFFFFu;
        unsigned long long a = ((unsigned long long)curw << 32) | left;
        unsigned long long b = ((unsigned long long)right << 32) | curw;
        unsigned o = curw;
#pragma unroll
        for (int k = 1; k <= 4; ++k) {
            o &= (unsigned)(a >> (32 - k));
            o &= (unsigned)(b >> k);
        }
        seh[dr][ow] = o;
    }
    __syncthreads();

    // vertical erode (pad 1 outside image)
    for (int i = tid; i < 32 * 8; i += 256) {
        int orow = i >> 3, ow = i & 7;
        unsigned o = 0xFFFFFFFFu;
#pragma unroll
        for (int k = 0; k < 9; ++k) {
            int gr = r0 + orow - 4 + k;
            unsigned v = (gr >= 0 && gr < W) ? seh[orow + k][ow] : 0xFFFFFFFFu;
            o &= v;
        }
        sfw[orow][ow] = o;
    }
    __syncthreads();

    // expand to f32, float4 stores
    float4* out4 = (float4*)out;
    for (int i = tid; i < 32 * 64; i += 256) {
        int orow = i >> 6;
        int c = (i & 63) << 2;
        unsigned wv = sfw[orow][c >> 5];
        int sh = c & 31;
        float4 o;
        o.x = ((wv >> (sh + 0)) & 1u) ? 1.0f : 0.0f;
        o.y = ((wv >> (sh + 1)) & 1u) ? 1.0f : 0.0f;
        o.z = ((wv >> (sh + 2)) & 1u) ? 1.0f : 0.0f;
        o.w = ((wv >> (sh + 3)) & 1u) ? 1.0f : 0.0f;
        out4[(((r0 + orow) << 11) + (wbase << 5) + c) >> 2] = o;
    }
}

// ---------------------------------------------------------------------------
extern "C" void kernel_launch(void* const* d_in, const int* in_sizes, int n_in,
                              void* d_out, int out_size) {
    const float* x  = (const float*)d_in[0];
    const float* bk = (const float*)d_in[1];
    float* out = (float*)d_out;

    dim3 gblur(W / 64, W / 32);
    k_blur<<<gblur, 256>>>(x, bk);
    k_select<<<NPAT * 2, 1024>>>();
    dim3 gclose(8, W / 32);
    k_close<<<gclose, 256>>>(out);
}

// round 11
// speedup vs baseline: 1.2721x; 1.0426x over previous
#include <cuda_runtime.h>
#include <stdint.h>

// ---------------------------------------------------------------------------
// BlurModel: 9x9 box blur -> per-patch sequential threshold search ->
// binarize -> morphological close, 2048x2048 f32.
// R11: blur raw-tile load vectorized to float4 (aligned, 4x fewer LDG);
//      select/close as R10. 3 launches.
// ---------------------------------------------------------------------------

#define W      2048
#define NPX    (W * W)
#define WORDS  64
#define NPAT   64
#define NB     8192
#define VLO    0.40f
#define VSC    40960.0f      // NB / 0.2
#define CAP    512

__device__ float    g_B[NPX];
__device__ unsigned g_hist[NPAT * NB];
__device__ int      g_done[NPAT];
__device__ float    g_vd[NPAT];
__device__ float    g_vu[NPAT];

// ---------------------------------------------------------------------------
__device__ __forceinline__ int bin_of(float v) {
    float f = (v - VLO) * VSC;
    int b = (int)floorf(f);
    return b < 0 ? 0 : (b > NB - 1 ? NB - 1 : b);
}

// ---------------------------------------------------------------------------
// K1: fused 9x9 separable box blur, register-blocked, float4 loads.
// Tile 64x32 out, halo 4. 256 threads, 2048 blocks. Also zeroes g_hist.
__global__ void k_blur(const float* __restrict__ x,
                       const float* __restrict__ kptr) {
    __shared__ __align__(16) float raw[40][72];
    __shared__ __align__(16) float hs[40][64];
    int c0 = blockIdx.x << 6;
    int r0 = blockIdx.y << 5;
    int bid = blockIdx.y * gridDim.x + blockIdx.x;
    int tid = threadIdx.x;
    float kf = __ldg(kptr);

    // zero this block's slice of g_hist (2048 blocks x 256 u32 = 2 MB)
    {
        unsigned* hz = g_hist + bid * 256;
        if (tid < 64) ((uint4*)hz)[tid] = make_uint4(0, 0, 0, 0);
        if (bid == 0 && tid < NPAT) g_done[tid] = 0;
    }

    // load raw tile (40 x 72) as float4: columns c0-4 .. c0+67, 4-aligned.
    // Out-of-range chunks at image borders are exactly aligned float4s.
    {
        const float4* x4 = (const float4*)x;
        for (int i = tid; i < 40 * 18; i += 256) {
            int rr = i / 18, q = i - rr * 18;
            int gr = r0 - 4 + rr;
            int gc = c0 - 4 + (q << 2);
            float4 v = make_float4(0.f, 0.f, 0.f, 0.f);
            if (gr >= 0 && gr < W && gc >= 0 && gc < W)
                v = x4[((gr << 11) + gc) >> 2];
            *(float4*)&raw[rr][q << 2] = v;
        }
    }
    __syncthreads();

    // horizontal 9-sum: each task = 4 adjacent outputs of one row.
    for (int i = tid; i < 40 * 16; i += 256) {
        int row = i >> 4, g = i & 15;
        int c = g << 2;
        const float4* rp = (const float4*)&raw[row][c];
        float4 a = rp[0], b = rp[1], d = rp[2];
        float f0 = a.x, f1 = a.y, f2 = a.z, f3 = a.w;
        float f4 = b.x, f5 = b.y, f6 = b.z, f7 = b.w;
        float f8 = d.x, f9 = d.y, f10 = d.z, f11 = d.w;
        float4 o;
        o.x = ((((((((f0 + f1) + f2) + f3) + f4) + f5) + f6) + f7) + f8);
        o.y = ((((((((f1 + f2) + f3) + f4) + f5) + f6) + f7) + f8) + f9);
        o.z = ((((((((f2 + f3) + f4) + f5) + f6) + f7) + f8) + f9) + f10);
        o.w = ((((((((f3 + f4) + f5) + f6) + f7) + f8) + f9) + f10) + f11);
        *(float4*)&hs[row][c] = o;
    }
    __syncthreads();

    // vertical 9-sum: thread = 8 consecutive output rows of one column.
    {
        int oc = tid & 63;
        int rg = tid >> 6;
        int base = rg << 3;
        float h[16];
#pragma unroll
        for (int k = 0; k < 16; ++k) h[k] = hs[base + k][oc];
        int gc = c0 + oc;
#pragma unroll
        for (int j = 0; j < 8; ++j) {
            float s = h[j];
#pragma unroll
            for (int k = 1; k < 9; ++k) s += h[j + k];
            int gr = r0 + base + j;
            g_B[(gr << 11) + gc] = s * kf;
        }
    }
}

// ---------------------------------------------------------------------------
__device__ float kth_largest(const float* a, int n, int k) {
    if (n <= 0) return 0.5f;
    if (k >= n) k = n - 1;
    for (int i = 0; i < n; ++i) {
        float v = a[i];
        int g = 0, e = 0;
        for (int j = 0; j < n; ++j) {
            if (a[j] > v) g++;
            else if (a[j] == v) e++;
        }
        if (g <= k && k < g + e) return v;
    }
    return a[0];
}

// K2: 128 blocks (2 per patch) x 1024 threads.
__global__ void k_select() {
    int blk = blockIdx.x;
    int p = blk >> 1;
    int half = blk & 1;
    int t = threadIdx.x;
    int lane = t & 31, wid = t >> 5;

    __shared__ unsigned hist[NB];          // 32 KB
    __shared__ unsigned warpSuf[32];
    __shared__ int s_binD, s_rD, s_binU, s_rU;
    __shared__ float listD[CAP];
    __shared__ float listU[CAP];
    __shared__ int cntD, cntU;
    __shared__ int sWho;

#pragma unroll
    for (int i = 0; i < NB / 1024; ++i) hist[t + i * 1024] = 0u;
    if (t == 0) { cntD = 0; cntU = 0; }
    __syncthreads();

    int prh = (((p >> 3) << 8) + (half << 7));
    int pc = (p & 7) << 8;
    const float4* B4 = (const float4*)g_B;

    // histogram of half patch: 128 rows x 256 cols = 8192 float4
    for (int i = t; i < 8192; i += 1024) {
        int rr = prh + (i >> 6);
        int cc = pc + ((i & 63) << 2);
        float4 v = B4[((rr << 11) + cc) >> 2];
        atomicAdd(&hist[bin_of(v.x)], 1u);
        atomicAdd(&hist[bin_of(v.y)], 1u);
        atomicAdd(&hist[bin_of(v.z)], 1u);
        atomicAdd(&hist[bin_of(v.w)], 1u);
    }
    __syncthreads();

    // merge to global per-patch hist (skip-zero, spread atomics)
    unsigned* gh = g_hist + p * NB;
#pragma unroll
    for (int i = 0; i < NB / 1024; ++i) {
        int idx = t + i * 1024;
        unsigned v = hist[idx];
        if (v) atomicAdd(&gh[idx], v);
    }
    __threadfence();
    __syncthreads();
    if (t == 0) sWho = atomicAdd(&g_done[p], 1);
    __syncthreads();
    if (sWho == 0) return;
    __threadfence();

    // reload merged histogram (L2 loads, bypass L1)
    {
        const uint4* gh4 = (const uint4*)gh;
        uint4* s4 = (uint4*)hist;
#pragma unroll
        for (int i = 0; i < NB / 4 / 1024; ++i) {
            uint4 v = __ldcg(&gh4[t + i * 1024]);
            s4[t + i * 1024] = v;
        }
    }
    __syncthreads();

    // segment sums: 8 bins per thread
    unsigned segv = 0;
#pragma unroll
    for (int b = 0; b < 8; ++b) segv += hist[t * 8 + b];

    // warp-level inclusive suffix sum
    unsigned suf = segv;
#pragma unroll
    for (int off = 1; off < 32; off <<= 1) {
        unsigned v = __shfl_down_sync(0xFFFFFFFFu, suf, off);
        if (lane + off < 32) suf += v;
    }
    unsigned wtot = __shfl_sync(0xFFFFFFFFu, suf, 0);
    if (lane == 0) warpSuf[wid] = wtot;
    __syncthreads();
    if (wid == 0) {
        unsigned tot = warpSuf[lane];
        unsigned ss = tot;
#pragma unroll
        for (int off = 1; off < 32; off <<= 1) {
            unsigned v = __shfl_down_sync(0xFFFFFFFFu, ss, off);
            if (lane + off < 32) ss += v;
        }
        warpSuf[lane] = ss - tot;
    }
    __syncthreads();

    unsigned incl = suf + warpSuf[wid];
    unsigned above = incl - segv;

    bool frame = (p < 8) || (p >= 56) || ((p & 7) == 0) || ((p & 7) == 7);
    float lo = frame ? (0.47f - 0.05f) : 0.47f;
    float hiT = 0.43f;
    const float inv = 1.0f / 65536.0f;
    int Clo = (int)ceilf(lo * 65536.0f);
    while ((float)Clo * inv < lo) Clo++;
    while (Clo > 0 && (float)(Clo - 1) * inv >= lo) Clo--;
    int Chi = (int)floorf(hiT * 65536.0f);
    while ((float)(Chi + 1) * inv <= hiT) Chi++;
    while (Chi > 0 && (float)Chi * inv > hiT) Chi--;
    int kd = Clo - 1;
    int ku = Chi;

    if ((unsigned)kd >= above && (unsigned)kd < incl) {
        unsigned S = above;
        for (int b = 7; b >= 0; --b) {
            unsigned hb = hist[t * 8 + b];
            if ((unsigned)kd < S + hb) { s_binD = t * 8 + b; s_rD = (int)((unsigned)kd - S); break; }
            S += hb;
        }
    }
    if ((unsigned)ku >= above && (unsigned)ku < incl) {
        unsigned S = above;
        for (int b = 7; b >= 0; --b) {
            unsigned hb = hist[t * 8 + b];
            if ((unsigned)ku < S + hb) { s_binU = t * 8 + b; s_rU = (int)((unsigned)ku - S); break; }
            S += hb;
        }
    }
    __syncthreads();

    // candidate collection over FULL patch (L2-resident reads)
    int binD = s_binD, binU = s_binU;
    int pr = (p >> 3) << 8;
    for (int i = t; i < 16384; i += 1024) {
        int rr = pr + (i >> 6);
        int cc = pc + ((i & 63) << 2);
        float4 v = B4[((rr << 11) + cc) >> 2];
        float vv[4] = {v.x, v.y, v.z, v.w};
#pragma unroll
        for (int q = 0; q < 4; ++q) {
            int b = bin_of(vv[q]);
            if (b == binD) {
                int pos = atomicAdd(&cntD, 1);
                if (pos < CAP) listD[pos] = vv[q];
            }
            if (binU != binD && b == binU) {
                int pos = atomicAdd(&cntU, 1);
                if (pos < CAP) listU[pos] = vv[q];
            }
        }
    }
    __syncthreads();

    if (t == 0) {
        int nD = cntD < CAP ? cntD : CAP;
        g_vd[p] = kth_largest(listD, nD, s_rD);
        if (binU == binD) {
            g_vu[p] = kth_largest(listD, nD, s_rU);
        } else {
            int nU = cntU < CAP ? cntU : CAP;
            g_vu[p] = kth_largest(listU, nU, s_rU);
        }
    }
}

// ---------------------------------------------------------------------------
// K3: fused close. Grid (8, 64) = 512 blocks: tile 256x32. 256 threads.
__global__ void k_close(float* __restrict__ out) {
    __shared__ unsigned sbin[48][12];
    __shared__ unsigned sdh[48][12];
    __shared__ unsigned sdv[40][12];
    __shared__ unsigned seh[40][8];
    __shared__ unsigned sfw[32][8];
    __shared__ float svd[NPAT], svu[NPAT];
    __shared__ float sth[NPAT];
    int wbase = blockIdx.x << 3;
    int r0 = blockIdx.y << 5;
    int tid = threadIdx.x;
    int warpId = tid >> 5, lane = tid & 31;

    if (tid < NPAT) { svd[tid] = g_vd[tid]; svu[tid] = g_vu[tid]; }
    __syncthreads();
    if (tid == 0) {
        float t = 0.5f;
        for (int p = 0; p < NPAT; ++p) {
            float vd = svd[p], vu = svu[p];
            int guard = 0;
            while (t >= vd && guard < 1000000) {
                guard++;
                bool jumped = false;
                if (t >= 0.25f && t < 1.0f) {
                    float bandlo = (t >= 0.5f) ? 0.5f : 0.25f;
                    int ulps     = (t >= 0.5f) ? 839 : 1678;
                    float tgt = fmaxf(vd, bandlo);
                    int mt = __float_as_int(t), mv = __float_as_int(tgt);
                    int kj = (mt - mv) / ulps - 1;
                    if (kj > 0) { t = __int_as_float(mt - kj * ulps); jumped = true; }
                }
                if (!jumped) t = t - 5e-5f;
            }
            guard = 0;
            while (t < vu && guard < 2000000) {
                guard++;
                bool jumped = false;
                if (t >= 0.25f && t < 1.0f) {
                    float bandhi = (t >= 0.5f) ? 1.0f : 0.5f;
                    int ulps     = (t >= 0.5f) ? 84 : 168;
                    float tgt = fminf(vu, bandhi);
                    int mt = __float_as_int(t), mv = __float_as_int(tgt);
                    int kj = (mv - mt) / ulps - 1;
                    if (kj > 0) { t = __int_as_float(mt + kj * ulps); jumped = true; }
                }
                if (!jumped) t = t + 5e-6f;
            }
            sth[p] = t;
        }
    }
    __syncthreads();

    // binarize 48 rows x 12 words
#pragma unroll 2
    for (int tsk = warpId; tsk < 48 * 3; tsk += 8) {
        int row = tsk / 3, qw = tsk - row * 3;
        int tw = (qw << 2) + (lane >> 3);
        int gw = wbase - 2 + tw;
        int gr = r0 - 8 + row;
        unsigned nib = 0;
        if (gr >= 0 && gr < W && gw >= 0 && gw < WORDS) {
            float th = sth[((gr >> 8) << 3) | (gw >> 3)];
            const float4* rp = (const float4*)(g_B + (gr << 11));
            float4 v = rp[(gw << 3) + (lane & 7)];
            nib = (unsigned)(v.x > th) | ((unsigned)(v.y > th) << 1)
                | ((unsigned)(v.z > th) << 2) | ((unsigned)(v.w > th) << 3);
        }
        unsigned x = nib | (__shfl_xor_sync(0xFFFFFFFFu, nib, 1) << 4);
        x = x | (__shfl_xor_sync(0xFFFFFFFFu, x, 2) << 8);
        x = x | (__shfl_xor_sync(0xFFFFFFFFu, x, 4) << 16);
        if ((lane & 7) == 0) sbin[row][tw] = x;
    }
    __syncthreads();

    // horizontal dilate (pad 0): j = 0..9
    for (int i = tid; i < 48 * 10; i += 256) {
        int row = i / 10, j = i - row * 10;
        unsigned curw = sbin[row][j + 1];
        unsigned left = sbin[row][j];
        unsigned right = sbin[row][j + 2];
        unsigned long long a = ((unsigned long long)curw << 32) | left;
        unsigned long long b = ((unsigned long long)right << 32) | curw;
        unsigned o = curw;
#pragma unroll
        for (int k = 1; k <= 4; ++k) {
            o |= (unsigned)(a >> (32 - k));
            o |= (unsigned)(b >> k);
        }
        sdh[row][j] = o;
    }
    __syncthreads();

    // vertical dilate (pad 0): dr = 0..39
    for (int i = tid; i < 40 * 10; i += 256) {
        int dr = i / 10, j = i - dr * 10;
        unsigned o = 0u;
#pragma unroll
        for (int k = 0; k < 9; ++k) o |= sdh[dr + k][j];
        sdv[dr][j] = o;
    }
    __syncthreads();

    // horizontal erode (pad 1 outside image)
    for (int i = tid; i < 40 * 8; i += 256) {
        int dr = i >> 3, ow = i & 7;
        unsigned curw = sdv[dr][ow + 1];
        unsigned left  = (wbase + ow - 1 >= 0)    ? sdv[dr][ow]     : 0xFFFFFFFFu;
        unsigned right = (wbase + ow + 1 < WORDS) ? sdv[dr][ow + 2] : 0xFFFFFFFFu;
        unsigned long long a = ((unsigned long long)curw << 32) | left;
        unsigned long long b = ((unsigned long long)right << 32) | curw;
        unsigned o = curw;
#pragma unroll
        for (int k = 1; k <= 4; ++k) {
            o &= (unsigned)(a >> (32 - k));
            o &= (unsigned)(b >> k);
        }
        seh[dr][ow] = o;
    }
    __syncthreads();

    // vertical erode (pad 1 outside image)
    for (int i = tid; i < 32 * 8; i += 256) {
        int orow = i >> 3, ow = i & 7;
        unsigned o = 0xFFFFFFFFu;
#pragma unroll
        for (int k = 0; k < 9; ++k) {
            int gr = r0 + orow - 4 + k;
            unsigned v = (gr >= 0 && gr < W) ? seh[orow + k][ow] : 0xFFFFFFFFu;
            o &= v;
        }
        sfw[orow][ow] = o;
    }
    __syncthreads();

    // expand to f32, float4 stores
    float4* out4 = (float4*)out;
    for (int i = tid; i < 32 * 64; i += 256) {
        int orow = i >> 6;
        int c = (i & 63) << 2;
        unsigned wv = sfw[orow][c >> 5];
        int sh = c & 31;
        float4 o;
        o.x = ((wv >> (sh + 0)) & 1u) ? 1.0f : 0.0f;
        o.y = ((wv >> (sh + 1)) & 1u) ? 1.0f : 0.0f;
        o.z = ((wv >> (sh + 2)) & 1u) ? 1.0f : 0.0f;
        o.w = ((wv >> (sh + 3)) & 1u) ? 1.0f : 0.0f;
        out4[(((r0 + orow) << 11) + (wbase << 5) + c) >> 2] = o;
    }
}

// ---------------------------------------------------------------------------
extern "C" void kernel_launch(void* const* d_in, const int* in_sizes, int n_in,
                              void* d_out, int out_size) {
    const float* x  = (const float*)d_in[0];
    const float* bk = (const float*)d_in[1];
    float* out = (float*)d_out;

    dim3 gblur(W / 64, W / 32);
    k_blur<<<gblur, 256>>>(x, bk);
    k_select<<<NPAT * 2, 1024>>>();
    dim3 gclose(8, W / 32);
    k_close<<<gclose, 256>>>(out);
}

// round 14
// speedup vs baseline: 1.2791x; 1.0055x over previous
#include <cuda_runtime.h>
#include <stdint.h>

// ---------------------------------------------------------------------------
// BlurModel: 9x9 box blur -> per-patch sequential threshold search ->
// binarize -> morphological close, 2048x2048 f32.
// R13 (= R12 resubmit after infra failure): blur horizontal pass reads
// global directly (no raw smem stage); close 512-thread 256x64 tiles.
// 3 launches.
// ---------------------------------------------------------------------------

#define W      2048
#define NPX    (W * W)
#define WORDS  64
#define NPAT   64
#define NB     8192
#define VLO    0.40f
#define VSC    40960.0f      // NB / 0.2
#define CAP    512

__device__ float    g_B[NPX];
__device__ unsigned g_hist[NPAT * NB];
__device__ int      g_done[NPAT];
__device__ float    g_vd[NPAT];
__device__ float    g_vu[NPAT];

// ---------------------------------------------------------------------------
__device__ __forceinline__ int bin_of(float v) {
    float f = (v - VLO) * VSC;
    int b = (int)floorf(f);
    return b < 0 ? 0 : (b > NB - 1 ? NB - 1 : b);
}

// ---------------------------------------------------------------------------
// K1: fused 9x9 separable box blur. Horizontal pass reads global float4
// directly; only hsum tile lives in smem. Tile 64x32 out, halo 4.
// 256 threads, 2048 blocks. Also zeroes g_hist slice.
__global__ void k_blur(const float* __restrict__ x,
                       const float* __restrict__ kptr) {
    __shared__ __align__(16) float hs[40][64];
    int c0 = blockIdx.x << 6;
    int r0 = blockIdx.y << 5;
    int bid = blockIdx.y * gridDim.x + blockIdx.x;
    int tid = threadIdx.x;
    float kf = __ldg(kptr);

    // zero this block's slice of g_hist (2048 blocks x 256 u32 = 2 MB)
    {
        unsigned* hz = g_hist + bid * 256;
        if (tid < 64) ((uint4*)hz)[tid] = make_uint4(0, 0, 0, 0);
        if (bid == 0 && tid < NPAT) g_done[tid] = 0;
    }

    // horizontal 9-sum: task = 4 adjacent outputs of one row, reading
    // global cols (c0+c-4 .. c0+c+7) as 3 aligned float4 (zero padded).
    {
        const float4* x4 = (const float4*)x;
        for (int i = tid; i < 40 * 16; i += 256) {
            int row = i >> 4, g = i & 15;
            int c = g << 2;
            int gr = r0 - 4 + row;
            int gbase = c0 + c - 4;
            float4 a = make_float4(0.f, 0.f, 0.f, 0.f);
            float4 b = a, d = a;
            if (gr >= 0 && gr < W) {
                const float4* rp = x4 + ((gr << 11) >> 2);
                if (gbase >= 0)          a = rp[(gbase     ) >> 2];
                                         b = rp[(gbase + 4 ) >> 2];
                if (gbase + 8 < W)       d = rp[(gbase + 8 ) >> 2];
            }
            float f0 = a.x, f1 = a.y, f2 = a.z, f3 = a.w;
            float f4 = b.x, f5 = b.y, f6 = b.z, f7 = b.w;
            float f8 = d.x, f9 = d.y, f10 = d.z, f11 = d.w;
            float4 o;
            o.x = ((((((((f0 + f1) + f2) + f3) + f4) + f5) + f6) + f7) + f8);
            o.y = ((((((((f1 + f2) + f3) + f4) + f5) + f6) + f7) + f8) + f9);
            o.z = ((((((((f2 + f3) + f4) + f5) + f6) + f7) + f8) + f9) + f10);
            o.w = ((((((((f3 + f4) + f5) + f6) + f7) + f8) + f9) + f10) + f11);
            *(float4*)&hs[row][c] = o;
        }
    }
    __syncthreads();

    // vertical 9-sum: thread = 8 consecutive output rows of one column.
    {
        int oc = tid & 63;
        int rg = tid >> 6;
        int base = rg << 3;
        float h[16];
#pragma unroll
        for (int k = 0; k < 16; ++k) h[k] = hs[base + k][oc];
        int gc = c0 + oc;
#pragma unroll
        for (int j = 0; j < 8; ++j) {
            float s = h[j];
#pragma unroll
            for (int k = 1; k < 9; ++k) s += h[j + k];
            int gr = r0 + base + j;
            g_B[(gr << 11) + gc] = s * kf;
        }
    }
}

// ---------------------------------------------------------------------------
__device__ float kth_largest(const float* a, int n, int k) {
    if (n <= 0) return 0.5f;
    if (k >= n) k = n - 1;
    for (int i = 0; i < n; ++i) {
        float v = a[i];
        int g = 0, e = 0;
        for (int j = 0; j < n; ++j) {
            if (a[j] > v) g++;
            else if (a[j] == v) e++;
        }
        if (g <= k && k < g + e) return v;
    }
    return a[0];
}

// K2: 128 blocks (2 per patch) x 1024 threads.
__global__ void k_select() {
    int blk = blockIdx.x;
    int p = blk >> 1;
    int half = blk & 1;
    int t = threadIdx.x;
    int lane = t & 31, wid = t >> 5;

    __shared__ unsigned hist[NB];          // 32 KB
    __shared__ unsigned warpSuf[32];
    __shared__ int s_binD, s_rD, s_binU, s_rU;
    __shared__ float listD[CAP];
    __shared__ float listU[CAP];
    __shared__ int cntD, cntU;
    __shared__ int sWho;

#pragma unroll
    for (int i = 0; i < NB / 1024; ++i) hist[t + i * 1024] = 0u;
    if (t == 0) { cntD = 0; cntU = 0; }
    __syncthreads();

    int prh = (((p >> 3) << 8) + (half << 7));
    int pc = (p & 7) << 8;
    const float4* B4 = (const float4*)g_B;

    // histogram of half patch: 128 rows x 256 cols = 8192 float4
    for (int i = t; i < 8192; i += 1024) {
        int rr = prh + (i >> 6);
        int cc = pc + ((i & 63) << 2);
        float4 v = B4[((rr << 11) + cc) >> 2];
        atomicAdd(&hist[bin_of(v.x)], 1u);
        atomicAdd(&hist[bin_of(v.y)], 1u);
        atomicAdd(&hist[bin_of(v.z)], 1u);
        atomicAdd(&hist[bin_of(v.w)], 1u);
    }
    __syncthreads();

    // merge to global per-patch hist (skip-zero, spread atomics)
    unsigned* gh = g_hist + p * NB;
#pragma unroll
    for (int i = 0; i < NB / 1024; ++i) {
        int idx = t + i * 1024;
        unsigned v = hist[idx];
        if (v) atomicAdd(&gh[idx], v);
    }
    __threadfence();
    __syncthreads();
    if (t == 0) sWho = atomicAdd(&g_done[p], 1);
    __syncthreads();
    if (sWho == 0) return;
    __threadfence();

    // reload merged histogram (L2 loads, bypass L1)
    {
        const uint4* gh4 = (const uint4*)gh;
        uint4* s4 = (uint4*)hist;
#pragma unroll
        for (int i = 0; i < NB / 4 / 1024; ++i) {
            uint4 v = __ldcg(&gh4[t + i * 1024]);
            s4[t + i * 1024] = v;
        }
    }
    __syncthreads();

    // segment sums: 8 bins per thread
    unsigned segv = 0;
#pragma unroll
    for (int b = 0; b < 8; ++b) segv += hist[t * 8 + b];

    // warp-level inclusive suffix sum
    unsigned suf = segv;
#pragma unroll
    for (int off = 1; off < 32; off <<= 1) {
        unsigned v = __shfl_down_sync(0xFFFFFFFFu, suf, off);
        if (lane + off < 32) suf += v;
    }
    unsigned wtot = __shfl_sync(0xFFFFFFFFu, suf, 0);
    if (lane == 0) warpSuf[wid] = wtot;
    __syncthreads();
    if (wid == 0) {
        unsigned tot = warpSuf[lane];
        unsigned ss = tot;
#pragma unroll
        for (int off = 1; off < 32; off <<= 1) {
            unsigned v = __shfl_down_sync(0xFFFFFFFFu, ss, off);
            if (lane + off < 32) ss += v;
        }
        warpSuf[lane] = ss - tot;
    }
    __syncthreads();

    unsigned incl = suf + warpSuf[wid];
    unsigned above = incl - segv;

    bool frame = (p < 8) || (p >= 56) || ((p & 7) == 0) || ((p & 7) == 7);
    float lo = frame ? (0.47f - 0.05f) : 0.47f;
    float hiT = 0.43f;
    const float inv = 1.0f / 65536.0f;
    int Clo = (int)ceilf(lo * 65536.0f);
    while ((float)Clo * inv < lo) Clo++;
    while (Clo > 0 && (float)(Clo - 1) * inv >= lo) Clo--;
    int Chi = (int)floorf(hiT * 65536.0f);
    while ((float)(Chi + 1) * inv <= hiT) Chi++;
    while (Chi > 0 && (float)Chi * inv > hiT) Chi--;
    int kd = Clo - 1;
    int ku = Chi;

    if ((unsigned)kd >= above && (unsigned)kd < incl) {
        unsigned S = above;
        for (int b = 7; b >= 0; --b) {
            unsigned hb = hist[t * 8 + b];
            if ((unsigned)kd < S + hb) { s_binD = t * 8 + b; s_rD = (int)((unsigned)kd - S); break; }
            S += hb;
        }
    }
    if ((unsigned)ku >= above && (unsigned)ku < incl) {
        unsigned S = above;
        for (int b = 7; b >= 0; --b) {
            unsigned hb = hist[t * 8 + b];
            if ((unsigned)ku < S + hb) { s_binU = t * 8 + b; s_rU = (int)((unsigned)ku - S); break; }
            S += hb;
        }
    }
    __syncthreads();

    // candidate collection over FULL patch (L2-resident reads)
    int binD = s_binD, binU = s_binU;
    int pr = (p >> 3) << 8;
    for (int i = t; i < 16384; i += 1024) {
        int rr = pr + (i >> 6);
        int cc = pc + ((i & 63) << 2);
        float4 v = B4[((rr << 11) + cc) >> 2];
        float vv[4] = {v.x, v.y, v.z, v.w};
#pragma unroll
        for (int q = 0; q < 4; ++q) {
            int b = bin_of(vv[q]);
            if (b == binD) {
                int pos = atomicAdd(&cntD, 1);
                if (pos < CAP) listD[pos] = vv[q];
            }
            if (binU != binD && b == binU) {
                int pos = atomicAdd(&cntU, 1);
                if (pos < CAP) listU[pos] = vv[q];
            }
        }
    }
    __syncthreads();

    if (t == 0) {
        int nD = cntD < CAP ? cntD : CAP;
        g_vd[p] = kth_largest(listD, nD, s_rD);
        if (binU == binD) {
            g_vu[p] = kth_largest(listD, nD, s_rU);
        } else {
            int nU = cntU < CAP ? cntU : CAP;
            g_vu[p] = kth_largest(listU, nU, s_rU);
        }
    }
}

// ---------------------------------------------------------------------------
// K3: fused close. Grid (8, 32) = 256 blocks: tile 256 cols x 64 rows.
// 512 threads. bin rows r0-8..r0+71 (80), words wbase-2..wbase+9 (12).
__global__ void k_close(float* __restrict__ out) {
    __shared__ unsigned sbin[80][12];
    __shared__ unsigned sdh[80][12];   // dilH: word j = global wbase-1+j, j=0..9
    __shared__ unsigned sdv[72][12];   // dilV: row dr = global r0-4+dr
    __shared__ unsigned seh[72][8];    // eroH
    __shared__ unsigned sfw[64][8];    // final words
    __shared__ float svd[NPAT], svu[NPAT];
    __shared__ float sth[NPAT];
    int wbase = blockIdx.x << 3;
    int r0 = blockIdx.y << 6;
    int tid = threadIdx.x;
    int warpId = tid >> 5, lane = tid & 31;

    if (tid < NPAT) { svd[tid] = g_vd[tid]; svu[tid] = g_vu[tid]; }
    __syncthreads();
    if (tid == 0) {
        float t = 0.5f;
        for (int p = 0; p < NPAT; ++p) {
            float vd = svd[p], vu = svu[p];
            int guard = 0;
            while (t >= vd && guard < 1000000) {
                guard++;
                bool jumped = false;
                if (t >= 0.25f && t < 1.0f) {
                    float bandlo = (t >= 0.5f) ? 0.5f : 0.25f;
                    int ulps     = (t >= 0.5f) ? 839 : 1678;
                    float tgt = fmaxf(vd, bandlo);
                    int mt = __float_as_int(t), mv = __float_as_int(tgt);
                    int kj = (mt - mv) / ulps - 1;
                    if (kj > 0) { t = __int_as_float(mt - kj * ulps); jumped = true; }
                }
                if (!jumped) t = t - 5e-5f;
            }
            guard = 0;
            while (t < vu && guard < 2000000) {
                guard++;
                bool jumped = false;
                if (t >= 0.25f && t < 1.0f) {
                    float bandhi = (t >= 0.5f) ? 1.0f : 0.5f;
                    int ulps     = (t >= 0.5f) ? 84 : 168;
                    float tgt = fminf(vu, bandhi);
                    int mt = __float_as_int(t), mv = __float_as_int(tgt);
                    int kj = (mv - mt) / ulps - 1;
                    if (kj > 0) { t = __int_as_float(mt + kj * ulps); jumped = true; }
                }
                if (!jumped) t = t + 5e-6f;
            }
            sth[p] = t;
        }
    }
    __syncthreads();

    // binarize 80 rows x 12 words: warp task = 4 words of one row
#pragma unroll 2
    for (int tsk = warpId; tsk < 80 * 3; tsk += 16) {
        int row = tsk / 3, qw = tsk - row * 3;
        int tw = (qw << 2) + (lane >> 3);
        int gw = wbase - 2 + tw;
        int gr = r0 - 8 + row;
        unsigned nib = 0;
        if (gr >= 0 && gr < W && gw >= 0 && gw < WORDS) {
            float th = sth[((gr >> 8) << 3) | (gw >> 3)];
            const float4* rp = (const float4*)(g_B + (gr << 11));
            float4 v = rp[(gw << 3) + (lane & 7)];
            nib = (unsigned)(v.x > th) | ((unsigned)(v.y > th) << 1)
                | ((unsigned)(v.z > th) << 2) | ((unsigned)(v.w > th) << 3);
        }
        unsigned x = nib | (__shfl_xor_sync(0xFFFFFFFFu, nib, 1) << 4);
        x = x | (__shfl_xor_sync(0xFFFFFFFFu, x, 2) << 8);
        x = x | (__shfl_xor_sync(0xFFFFFFFFu, x, 4) << 16);
        if ((lane & 7) == 0) sbin[row][tw] = x;
    }
    __syncthreads();

    // horizontal dilate (pad 0): j = 0..9
    for (int i = tid; i < 80 * 10; i += 512) {
        int row = i / 10, j = i - row * 10;
        unsigned curw = sbin[row][j + 1];
        unsigned left = sbin[row][j];
        unsigned right = sbin[row][j + 2];
        unsigned long long a = ((unsigned long long)curw << 32) | left;
        unsigned long long b = ((unsigned long long)right << 32) | curw;
        unsigned o = curw;
#pragma unroll
        for (int k = 1; k <= 4; ++k) {
            o |= (unsigned)(a >> (32 - k));
            o |= (unsigned)(b >> k);
        }
        sdh[row][j] = o;
    }
    __syncthreads();

    // vertical dilate (pad 0): dr = 0..71
    for (int i = tid; i < 72 * 10; i += 512) {
        int dr = i / 10, j = i - dr * 10;
        unsigned o = 0u;
#pragma unroll
        for (int k = 0; k < 9; ++k) o |= sdh[dr + k][j];
        sdv[dr][j] = o;
    }
    __syncthreads();

    // horizontal erode (pad 1 outside image)
    for (int i = tid; i < 72 * 8; i += 512) {
        int dr = i >> 3, ow = i & 7;
        unsigned curw = sdv[dr][ow + 1];
        unsigned left  = (wbase + ow - 1 >= 0)    ? sdv[dr][ow]     : 0xFFFFFFFFu;
        unsigned right = (wbase + ow + 1 < WORDS) ? sdv[dr][ow + 2] : 0xFFFFFFFFu;
        unsigned long long a = ((unsigned long long)curw << 32) | left;
        unsigned long long b = ((unsigned long long)right << 32) | curw;
        unsigned o = curw;
#pragma unroll
        for (int k = 1; k <= 4; ++k) {
            o &= (unsigned)(a >> (32 - k));
            o &= (unsigned)(b >> k);
        }
        seh[dr][ow] = o;
    }
    __syncthreads();

    // vertical erode (pad 1 outside image): out rows 0..63
    for (int i = tid; i < 64 * 8; i += 512) {
        int orow = i >> 3, ow = i & 7;
        unsigned o = 0xFFFFFFFFu;
#pragma unroll
        for (int k = 0; k < 9; ++k) {
            int gr = r0 + orow - 4 + k;
            unsigned v = (gr >= 0 && gr < W) ? seh[orow + k][ow] : 0xFFFFFFFFu;
            o &= v;
        }
        sfw[orow][ow] = o;
    }
    __syncthreads();

    // expand to f32, float4 stores (64 rows x 64 quads)
    float4* out4 = (float4*)out;
    for (int i = tid; i < 64 * 64; i += 512) {
        int orow = i >> 6;
        int c = (i & 63) << 2;
        unsigned wv = sfw[orow][c >> 5];
        int sh = c & 31;
        float4 o;
        o.x = ((wv >> (sh + 0)) & 1u) ? 1.0f : 0.0f;
        o.y = ((wv >> (sh + 1)) & 1u) ? 1.0f : 0.0f;
        o.z = ((wv >> (sh + 2)) & 1u) ? 1.0f : 0.0f;
        o.w = ((wv >> (sh + 3)) & 1u) ? 1.0f : 0.0f;
        out4[(((r0 + orow) << 11) + (wbase << 5) + c) >> 2] = o;
    }
}

// ---------------------------------------------------------------------------
extern "C" void kernel_launch(void* const* d_in, const int* in_sizes, int n_in,
                              void* d_out, int out_size) {
    const float* x  = (const float*)d_in[0];
    const float* bk = (const float*)d_in[1];
    float* out = (float*)d_out;

    dim3 gblur(W / 64, W / 32);
    k_blur<<<gblur, 256>>>(x, bk);
    k_select<<<NPAT * 2, 1024>>>();
    dim3 gclose(8, W / 64);
    k_close<<<gclose, 512>>>(out);
}